// round 5
// baseline (speedup 1.0000x reference)
#include <cuda_runtime.h>
#include <cuda_bf16.h>
#include <stdint.h>
#include <math.h>

#define SS 8192
#define DD 1024
#define HH 16
#define HDIM 64

// Scratch (static device arrays -- no allocation in kernel_launch)
__device__ float g_Q[SS * DD];
__device__ float g_K[SS * DD];
__device__ float g_V[SS * DD];
__device__ float g_O[SS * DD];

// ===========================================================================
// PTX helpers (baseline ISA only: ldmatrix + mma.sync, sm_80+)
// ===========================================================================
__device__ __forceinline__ uint32_t smem_u32(const void* p) {
    uint32_t a;
    asm("{ .reg .u64 t; cvta.to.shared.u64 t, %1; cvt.u32.u64 %0, t; }"
        : "=r"(a) : "l"(p));
    return a;
}

#define LDSM_X4(r0, r1, r2, r3, addr)                                       \
    asm volatile(                                                           \
        "ldmatrix.sync.aligned.m8n8.x4.shared.b16 {%0, %1, %2, %3}, [%4];"  \
        : "=r"(r0), "=r"(r1), "=r"(r2), "=r"(r3) : "r"(addr))

#define MMA16816(d, a, b)                                                   \
    asm volatile(                                                           \
        "mma.sync.aligned.m16n8k16.row.col.f32.bf16.bf16.f32 "              \
        "{%0, %1, %2, %3}, {%4, %5, %6, %7}, {%8, %9}, {%0, %1, %2, %3};"   \
        : "+f"((d)[0]), "+f"((d)[1]), "+f"((d)[2]), "+f"((d)[3])            \
        : "r"((a)[0]), "r"((a)[1]), "r"((a)[2]), "r"((a)[3]),               \
          "r"((b)[0]), "r"((b)[1]))

// ===========================================================================
// mma.sync GEMM with bf16x3 emulated-fp32:
//   C[m,n] = sum_k A[m,k] * W[n,k] + bias[n]
// A: 8192x1024 row-major, W: 1024x1024 row-major (k contiguous = B col-major).
// CTA tile 128x128, K-chunk 64, 256 threads (8 warps, each 32m x 64n).
// Products per step: Ahi*Bhi + Ahi*Blo + Alo*Bhi  (fp32 accum).
// ===========================================================================
#define OFF_BIAS 0
#define OFF_AH   1024
#define OFF_AL   (1024 + 16384)
#define OFF_BH   (1024 + 32768)
#define OFF_BL   (1024 + 49152)
#define GEMM_SMEM (1024 + 65536)

#define SWZ(o) ((o) ^ (((o) >> 3) & 0x70))

__device__ __forceinline__ void cvt_split(float4 v, uint2& hi, uint2& lo) {
    __nv_bfloat16 hx = __float2bfloat16(v.x);
    __nv_bfloat16 hy = __float2bfloat16(v.y);
    __nv_bfloat16 hz = __float2bfloat16(v.z);
    __nv_bfloat16 hw = __float2bfloat16(v.w);
    __nv_bfloat16 lx = __float2bfloat16(v.x - __bfloat162float(hx));
    __nv_bfloat16 ly = __float2bfloat16(v.y - __bfloat162float(hy));
    __nv_bfloat16 lz = __float2bfloat16(v.z - __bfloat162float(hz));
    __nv_bfloat16 lw = __float2bfloat16(v.w - __bfloat162float(hw));
    __nv_bfloat162 h01, h23, l01, l23;
    h01.x = hx; h01.y = hy; h23.x = hz; h23.y = hw;
    l01.x = lx; l01.y = ly; l23.x = lz; l23.y = lw;
    hi.x = *(uint32_t*)&h01; hi.y = *(uint32_t*)&h23;
    lo.x = *(uint32_t*)&l01; lo.y = *(uint32_t*)&l23;
}

__global__ __launch_bounds__(256)
void gemm_mma(const float* __restrict__ A, const float* __restrict__ W,
              const float* __restrict__ bias, float* __restrict__ C) {
    extern __shared__ char sm[];
    const uint32_t sbase = smem_u32(sm);
    float* sbias = (float*)(sm + OFF_BIAS);

    const int tid = threadIdx.x;
    const int wid = tid >> 5, lane = tid & 31;
    const int n0 = blockIdx.x * 128, m0 = blockIdx.y * 128;

    if (tid < 128) sbias[tid] = bias[n0 + tid];

    const int wm = (wid & 3) * 32;    // warp m-offset in tile
    const int wn = (wid >> 2) * 64;   // warp n-offset in tile

    float acc[2][8][4];
#pragma unroll
    for (int mt = 0; mt < 2; mt++)
#pragma unroll
        for (int nt = 0; nt < 8; nt++)
#pragma unroll
            for (int e = 0; e < 4; e++) acc[mt][nt][e] = 0.f;

    // conversion-load assignment: thread -> half row (32 floats)
    const int cr = tid >> 1;
    const int hc = (tid & 1) * 32;
    const float* pa = A + (size_t)(m0 + cr) * DD + hc;
    const float* pb = W + (size_t)(n0 + cr) * DD + hc;

    // ldmatrix lane address components
    const int local = lane & 7, sel = lane >> 3;

    for (int c = 0; c < DD / 64; c++) {
        // ---- stage chunk: fp32 -> bf16 hi/lo, swizzled smem ----
#pragma unroll
        for (int j = 0; j < 8; j++) {
            float4 av = *(const float4*)(pa + c * 64 + 4 * j);
            float4 bv = *(const float4*)(pb + c * 64 + 4 * j);
            uint32_t off = SWZ((uint32_t)(cr * 128 + (hc + 4 * j) * 2));
            uint2 ahi, alo, bhi, blo;
            cvt_split(av, ahi, alo);
            cvt_split(bv, bhi, blo);
            *(uint2*)(sm + OFF_AH + off) = ahi;
            *(uint2*)(sm + OFF_AL + off) = alo;
            *(uint2*)(sm + OFF_BH + off) = bhi;
            *(uint2*)(sm + OFF_BL + off) = blo;
        }
        __syncthreads();

#pragma unroll
        for (int kk = 0; kk < 64; kk += 16) {
            // ---- A fragments (m16 x k16 per ldmatrix.x4) ----
            uint32_t ah[2][4], al[2][4];
#pragma unroll
            for (int mt = 0; mt < 2; mt++) {
                const int row = wm + mt * 16 + local + (sel & 1) * 8;
                const int kb = kk + (sel >> 1) * 8;
                const uint32_t off = SWZ((uint32_t)(row * 128 + kb * 2));
                LDSM_X4(ah[mt][0], ah[mt][1], ah[mt][2], ah[mt][3],
                        sbase + OFF_AH + off);
                LDSM_X4(al[mt][0], al[mt][1], al[mt][2], al[mt][3],
                        sbase + OFF_AL + off);
            }
            // ---- B fragments (2 n-tiles per ldmatrix.x4) ----
            uint32_t bh[8][2], bl[8][2];
#pragma unroll
            for (int np = 0; np < 4; np++) {
                const int row = wn + np * 16 + (sel >> 1) * 8 + local;
                const int kb = kk + (sel & 1) * 8;
                const uint32_t off = SWZ((uint32_t)(row * 128 + kb * 2));
                uint32_t t0, t1, t2, t3;
                LDSM_X4(t0, t1, t2, t3, sbase + OFF_BH + off);
                bh[2 * np][0] = t0; bh[2 * np][1] = t1;
                bh[2 * np + 1][0] = t2; bh[2 * np + 1][1] = t3;
                LDSM_X4(t0, t1, t2, t3, sbase + OFF_BL + off);
                bl[2 * np][0] = t0; bl[2 * np][1] = t1;
                bl[2 * np + 1][0] = t2; bl[2 * np + 1][1] = t3;
            }
            // ---- 3-product MMAs ----
#pragma unroll
            for (int mt = 0; mt < 2; mt++)
#pragma unroll
                for (int nt = 0; nt < 8; nt++) {
                    MMA16816(acc[mt][nt], ah[mt], bh[nt]);
                    MMA16816(acc[mt][nt], ah[mt], bl[nt]);
                    MMA16816(acc[mt][nt], al[mt], bh[nt]);
                }
        }
        __syncthreads();
    }

    // ---- epilogue: acc + bias -> C ----
    const int er = lane >> 2;
    const int ec = (lane & 3) * 2;
#pragma unroll
    for (int mt = 0; mt < 2; mt++) {
#pragma unroll
        for (int nt = 0; nt < 8; nt++) {
            const int ct = wn + nt * 8 + ec;
            const int row0 = m0 + wm + mt * 16 + er;
            float2 v0, v1;
            v0.x = acc[mt][nt][0] + sbias[ct];
            v0.y = acc[mt][nt][1] + sbias[ct + 1];
            v1.x = acc[mt][nt][2] + sbias[ct];
            v1.y = acc[mt][nt][3] + sbias[ct + 1];
            *(float2*)&C[(size_t)row0 * DD + n0 + ct] = v0;
            *(float2*)&C[(size_t)(row0 + 8) * DD + n0 + ct] = v1;
        }
    }
}

// ===========================================================================
// Sliding-window flash attention (fp32, online softmax) -- unchanged (passing)
// ===========================================================================
#define QTILE 128
#define KTILE 64
#define LDPAD 68

__global__ __launch_bounds__(256, 2)
void attn_kernel(const float* __restrict__ Qg, const float* __restrict__ Kg,
                 const float* __restrict__ Vg, float* __restrict__ Og) {
    extern __shared__ float smf[];
    float* sQ = smf;
    float* sK = sQ + QTILE * LDPAD;
    float* sV = sK + KTILE * LDPAD;
    float* sP = sV + KTILE * LDPAD;

    const int tid = threadIdx.x;
    const int qs = blockIdx.x * QTILE;
    const int hoff = blockIdx.y * HDIM;

    const int kg = tid & 7;
    const int qg = tid >> 3;
    const int q0 = qg * 4;

    {
        const int r = tid >> 1;
        const int half = (tid & 1) * 32;
        const float* src = Qg + (size_t)(qs + r) * DD + hoff + half;
        float* dst = sQ + r * LDPAD + half;
#pragma unroll
        for (int j = 0; j < 8; j++)
            *(float4*)(dst + 4 * j) = *(const float4*)(src + 4 * j);
    }

    float m[4], l[4], o[4][8];
#pragma unroll
    for (int i = 0; i < 4; i++) {
        m[i] = -1e30f; l[i] = 0.f;
#pragma unroll
        for (int d = 0; d < 8; d++) o[i][d] = 0.f;
    }
    __syncthreads();

    for (int t = 0; t < 18; t++) {
        const int kt = qs - 512 + 64 * t;
        if (kt >= SS || kt + KTILE <= 0) continue;

        {
            const int r = tid >> 2;
            const int cw = (tid & 3) * 16;
            const int kabs = kt + r;
            float* kdst = sK + r * LDPAD + cw;
            float* vdst = sV + r * LDPAD + cw;
            if (kabs >= 0 && kabs < SS) {
                const float* kp = Kg + (size_t)kabs * DD + hoff + cw;
                const float* vp = Vg + (size_t)kabs * DD + hoff + cw;
#pragma unroll
                for (int j = 0; j < 4; j++) {
                    *(float4*)(kdst + 4 * j) = *(const float4*)(kp + 4 * j);
                    *(float4*)(vdst + 4 * j) = *(const float4*)(vp + 4 * j);
                }
            } else {
                const float4 z = make_float4(0.f, 0.f, 0.f, 0.f);
#pragma unroll
                for (int j = 0; j < 4; j++) {
                    *(float4*)(kdst + 4 * j) = z;
                    *(float4*)(vdst + 4 * j) = z;
                }
            }
        }
        __syncthreads();

        float acc[4][8];
#pragma unroll
        for (int i = 0; i < 4; i++)
#pragma unroll
            for (int j = 0; j < 8; j++) acc[i][j] = 0.f;

#pragma unroll
        for (int d4 = 0; d4 < HDIM; d4 += 4) {
            float4 qv[4];
#pragma unroll
            for (int i = 0; i < 4; i++)
                qv[i] = *(const float4*)&sQ[(q0 + i) * LDPAD + d4];
#pragma unroll
            for (int j = 0; j < 8; j++) {
                float4 kv = *(const float4*)&sK[(kg + 8 * j) * LDPAD + d4];
#pragma unroll
                for (int i = 0; i < 4; i++) {
                    acc[i][j] += qv[i].x * kv.x;
                    acc[i][j] += qv[i].y * kv.y;
                    acc[i][j] += qv[i].z * kv.z;
                    acc[i][j] += qv[i].w * kv.w;
                }
            }
        }

#pragma unroll
        for (int i = 0; i < 4; i++) {
            const int qabs = qs + q0 + i;
            float s[8];
            float rmax = -1e30f;
#pragma unroll
            for (int j = 0; j < 8; j++) {
                const int kabs = kt + kg + 8 * j;
                const bool ok = (kabs >= 0) & (kabs < SS) &
                                (kabs >= qabs - 512) & (kabs < qabs + 512);
                s[j] = ok ? acc[i][j] * 0.125f : -1e30f;
                rmax = fmaxf(rmax, s[j]);
            }
            rmax = fmaxf(rmax, __shfl_xor_sync(0xffffffffu, rmax, 1));
            rmax = fmaxf(rmax, __shfl_xor_sync(0xffffffffu, rmax, 2));
            rmax = fmaxf(rmax, __shfl_xor_sync(0xffffffffu, rmax, 4));
            const float mn = fmaxf(m[i], rmax);
            float rsum = 0.f;
#pragma unroll
            for (int j = 0; j < 8; j++) {
                const float p = (s[j] > -5e29f) ? __expf(s[j] - mn) : 0.f;
                rsum += p;
                sP[(q0 + i) * LDPAD + kg + 8 * j] = p;
            }
            rsum += __shfl_xor_sync(0xffffffffu, rsum, 1);
            rsum += __shfl_xor_sync(0xffffffffu, rsum, 2);
            rsum += __shfl_xor_sync(0xffffffffu, rsum, 4);
            const float alpha = __expf(m[i] - mn);
            l[i] = l[i] * alpha + rsum;
            m[i] = mn;
#pragma unroll
            for (int d = 0; d < 8; d++) o[i][d] *= alpha;
        }
        __syncthreads();

#pragma unroll
        for (int k4 = 0; k4 < KTILE; k4 += 4) {
            float pk[4][4];
#pragma unroll
            for (int i = 0; i < 4; i++) {
                float4 pv = *(const float4*)&sP[(q0 + i) * LDPAD + k4];
                pk[i][0] = pv.x; pk[i][1] = pv.y; pk[i][2] = pv.z; pk[i][3] = pv.w;
            }
#pragma unroll
            for (int kk = 0; kk < 4; kk++) {
                float4 va = *(const float4*)&sV[(k4 + kk) * LDPAD + kg * 8];
                float4 vb = *(const float4*)&sV[(k4 + kk) * LDPAD + kg * 8 + 4];
#pragma unroll
                for (int i = 0; i < 4; i++) {
                    o[i][0] += pk[i][kk] * va.x;
                    o[i][1] += pk[i][kk] * va.y;
                    o[i][2] += pk[i][kk] * va.z;
                    o[i][3] += pk[i][kk] * va.w;
                    o[i][4] += pk[i][kk] * vb.x;
                    o[i][5] += pk[i][kk] * vb.y;
                    o[i][6] += pk[i][kk] * vb.z;
                    o[i][7] += pk[i][kk] * vb.w;
                }
            }
        }
        __syncthreads();
    }

#pragma unroll
    for (int i = 0; i < 4; i++) {
        const int qabs = qs + q0 + i;
        float w = 1.f;
        if (qabs >= SS - 128) w = 1.f + (float)(qabs - (SS - 128)) * (1.f / 127.f);
        const float sc = w / l[i];
        float* dst = Og + (size_t)qabs * DD + hoff + kg * 8;
        float4 oa, ob;
        oa.x = o[i][0] * sc; oa.y = o[i][1] * sc; oa.z = o[i][2] * sc; oa.w = o[i][3] * sc;
        ob.x = o[i][4] * sc; ob.y = o[i][5] * sc; ob.z = o[i][6] * sc; ob.w = o[i][7] * sc;
        *(float4*)(dst + 0) = oa;
        *(float4*)(dst + 4) = ob;
    }
}

// ===========================================================================
extern "C" void kernel_launch(void* const* d_in, const int* in_sizes, int n_in,
                              void* d_out, int out_size) {
    // Bind inputs by size (robust to metadata ordering):
    const float* x = nullptr;
    const float* Wm[4] = {nullptr, nullptr, nullptr, nullptr};
    const float* bm[4] = {nullptr, nullptr, nullptr, nullptr};
    int nw = 0, nb = 0;
    for (int i = 0; i < n_in; i++) {
        const float* p = (const float*)d_in[i];
        if (in_sizes[i] == SS * DD) x = p;
        else if (in_sizes[i] == DD * DD) { if (nw < 4) Wm[nw++] = p; }
        else if (in_sizes[i] == DD) { if (nb < 4) bm[nb++] = p; }
    }
    const float *Wq = Wm[0], *Wk = Wm[1], *Wv = Wm[2], *Wo = Wm[3];
    const float *bq = bm[0], *bk = bm[1], *bvv = bm[2], *bo = bm[3];
    float* out = (float*)d_out;

    float *Qp, *Kp, *Vp, *Op;
    cudaGetSymbolAddress((void**)&Qp, g_Q);
    cudaGetSymbolAddress((void**)&Kp, g_K);
    cudaGetSymbolAddress((void**)&Vp, g_V);
    cudaGetSymbolAddress((void**)&Op, g_O);

    cudaFuncSetAttribute(gemm_mma, cudaFuncAttributeMaxDynamicSharedMemorySize,
                         GEMM_SMEM);

    dim3 ggrid(DD / 128, SS / 128);   // (8, 64)
    gemm_mma<<<ggrid, 256, GEMM_SMEM>>>(x, Wq, bq, Qp);
    gemm_mma<<<ggrid, 256, GEMM_SMEM>>>(x, Wk, bk, Kp);
    gemm_mma<<<ggrid, 256, GEMM_SMEM>>>(x, Wv, bvv, Vp);

    const size_t shmem = (size_t)(QTILE + KTILE + KTILE + QTILE) * LDPAD * sizeof(float);
    cudaFuncSetAttribute(attn_kernel, cudaFuncAttributeMaxDynamicSharedMemorySize,
                         (int)shmem);
    attn_kernel<<<dim3(SS / QTILE, HH), 256, shmem>>>(Qp, Kp, Vp, Op);

    gemm_mma<<<ggrid, 256, GEMM_SMEM>>>(Op, Wo, bo, out);
}

// round 7
// speedup vs baseline: 1.9414x; 1.9414x over previous
#include <cuda_runtime.h>
#include <cuda_bf16.h>
#include <stdint.h>
#include <math.h>

#define SS 8192
#define DD 1024
#define HH 16
#define HDIM 64

// ---- scratch: bf16 hi/lo pairs (static device arrays) ----
__device__ __nv_bfloat16 g_xh[SS * DD], g_xl[SS * DD];
__device__ __nv_bfloat16 g_Wh[4][DD * DD], g_Wl[4][DD * DD];
__device__ __nv_bfloat16 g_Qh[SS * DD], g_Ql[SS * DD];
__device__ __nv_bfloat16 g_Kh[SS * DD], g_Kl[SS * DD];
__device__ __nv_bfloat16 g_Vh[SS * DD], g_Vl[SS * DD];
__device__ __nv_bfloat16 g_Oh[SS * DD], g_Ol[SS * DD];

// ===========================================================================
// PTX helpers (baseline ISA: ldmatrix + mma.sync, sm_80+)
// ===========================================================================
__device__ __forceinline__ uint32_t smem_u32(const void* p) {
    uint32_t a;
    asm("{ .reg .u64 t; cvta.to.shared.u64 t, %1; cvt.u32.u64 %0, t; }"
        : "=r"(a) : "l"(p));
    return a;
}

#define LDSM_X4(r0, r1, r2, r3, addr)                                       \
    asm volatile(                                                           \
        "ldmatrix.sync.aligned.m8n8.x4.shared.b16 {%0, %1, %2, %3}, [%4];"  \
        : "=r"(r0), "=r"(r1), "=r"(r2), "=r"(r3) : "r"(addr))

#define LDSM_X4_T(r0, r1, r2, r3, addr)                                     \
    asm volatile(                                                           \
        "ldmatrix.sync.aligned.m8n8.x4.trans.shared.b16 {%0, %1, %2, %3}, [%4];" \
        : "=r"(r0), "=r"(r1), "=r"(r2), "=r"(r3) : "r"(addr))

#define MMA16816(d, a, b)                                                   \
    asm volatile(                                                           \
        "mma.sync.aligned.m16n8k16.row.col.f32.bf16.bf16.f32 "              \
        "{%0, %1, %2, %3}, {%4, %5, %6, %7}, {%8, %9}, {%0, %1, %2, %3};"   \
        : "+f"((d)[0]), "+f"((d)[1]), "+f"((d)[2]), "+f"((d)[3])            \
        : "r"((a)[0]), "r"((a)[1]), "r"((a)[2]), "r"((a)[3]),               \
          "r"((b)[0]), "r"((b)[1]))

#define SWZ(o) ((o) ^ (((o) >> 3) & 0x70))

__device__ __forceinline__ uint32_t packbf(float x, float y) {
    __nv_bfloat162 t;
    t.x = __float2bfloat16(x);
    t.y = __float2bfloat16(y);
    return *(uint32_t*)&t;
}
__device__ __forceinline__ float bflo(float x) {
    return x - __bfloat162float(__float2bfloat16(x));
}

// ===========================================================================
// fp32 -> bf16 hi/lo split (one pass, vectorized x8)
// ===========================================================================
__global__ void split_k(const float* __restrict__ in,
                        __nv_bfloat16* __restrict__ hi,
                        __nv_bfloat16* __restrict__ lo, int n8) {
    int i = blockIdx.x * blockDim.x + threadIdx.x;
    if (i >= n8) return;
    const float4* p = (const float4*)in + (size_t)i * 2;
    float4 v0 = p[0], v1 = p[1];
    float v[8] = {v0.x, v0.y, v0.z, v0.w, v1.x, v1.y, v1.z, v1.w};
    __nv_bfloat16 h[8], l[8];
#pragma unroll
    for (int j = 0; j < 8; j++) {
        h[j] = __float2bfloat16(v[j]);
        l[j] = __float2bfloat16(v[j] - __bfloat162float(h[j]));
    }
    ((uint4*)hi)[i] = *(uint4*)h;
    ((uint4*)lo)[i] = *(uint4*)l;
}

// ===========================================================================
// mma.sync GEMM, bf16x3 emulated-fp32, pre-split inputs:
//   C[m,n] = sum_k A[m,k]*W[n,k] + bias[n]
// If splitout: writes bf16 hi/lo pair arrays; else fp32 C.
// CTA 128x128, K-chunk 64, 256 threads (8 warps of 32m x 64n).
// ===========================================================================
#define OFF_BIAS 0
#define OFF_AH   1024
#define OFF_AL   (1024 + 16384)
#define OFF_BH   (1024 + 32768)
#define OFF_BL   (1024 + 49152)
#define GEMM_SMEM (1024 + 65536)

__global__ __launch_bounds__(256)
void gemm_mma(const __nv_bfloat16* __restrict__ Ah,
              const __nv_bfloat16* __restrict__ Al,
              const __nv_bfloat16* __restrict__ Bh,
              const __nv_bfloat16* __restrict__ Bl,
              const float* __restrict__ bias,
              float* __restrict__ C,
              __nv_bfloat16* __restrict__ Ch,
              __nv_bfloat16* __restrict__ Cl,
              int splitout) {
    extern __shared__ char sm[];
    const uint32_t sbase = smem_u32(sm);
    float* sbias = (float*)(sm + OFF_BIAS);

    const int tid = threadIdx.x;
    const int wid = tid >> 5, lane = tid & 31;
    const int n0 = blockIdx.x * 128, m0 = blockIdx.y * 128;

    if (tid < 128) sbias[tid] = bias[n0 + tid];

    const int wm = (wid & 3) * 32;
    const int wn = (wid >> 2) * 64;

    float acc[2][8][4];
#pragma unroll
    for (int mt = 0; mt < 2; mt++)
#pragma unroll
        for (int nt = 0; nt < 8; nt++)
#pragma unroll
            for (int e = 0; e < 4; e++) acc[mt][nt][e] = 0.f;

    const int cr = tid >> 1;
    const int hc = (tid & 1) * 32;   // bf16 elements
    const int localr = lane & 7, sel = lane >> 3;

    for (int c = 0; c < DD / 64; c++) {
        const size_t gb = (size_t)c * 64 + hc;
#pragma unroll
        for (int j = 0; j < 4; j++) {
            uint32_t off = SWZ((uint32_t)(cr * 128 + (hc + 8 * j) * 2));
            *(uint4*)(sm + OFF_AH + off) =
                *(const uint4*)&Ah[(size_t)(m0 + cr) * DD + gb + 8 * j];
            *(uint4*)(sm + OFF_AL + off) =
                *(const uint4*)&Al[(size_t)(m0 + cr) * DD + gb + 8 * j];
            *(uint4*)(sm + OFF_BH + off) =
                *(const uint4*)&Bh[(size_t)(n0 + cr) * DD + gb + 8 * j];
            *(uint4*)(sm + OFF_BL + off) =
                *(const uint4*)&Bl[(size_t)(n0 + cr) * DD + gb + 8 * j];
        }
        __syncthreads();

#pragma unroll
        for (int kk = 0; kk < 64; kk += 16) {
            uint32_t ah[2][4], al[2][4];
#pragma unroll
            for (int mt = 0; mt < 2; mt++) {
                const int row = wm + mt * 16 + localr + (sel & 1) * 8;
                const int kb = kk + (sel >> 1) * 8;
                const uint32_t off = SWZ((uint32_t)(row * 128 + kb * 2));
                LDSM_X4(ah[mt][0], ah[mt][1], ah[mt][2], ah[mt][3],
                        sbase + OFF_AH + off);
                LDSM_X4(al[mt][0], al[mt][1], al[mt][2], al[mt][3],
                        sbase + OFF_AL + off);
            }
            uint32_t bh[8][2], bl[8][2];
#pragma unroll
            for (int np = 0; np < 4; np++) {
                const int row = wn + np * 16 + (sel >> 1) * 8 + localr;
                const int kb = kk + (sel & 1) * 8;
                const uint32_t off = SWZ((uint32_t)(row * 128 + kb * 2));
                uint32_t t0, t1, t2, t3;
                LDSM_X4(t0, t1, t2, t3, sbase + OFF_BH + off);
                bh[2 * np][0] = t0; bh[2 * np][1] = t1;
                bh[2 * np + 1][0] = t2; bh[2 * np + 1][1] = t3;
                LDSM_X4(t0, t1, t2, t3, sbase + OFF_BL + off);
                bl[2 * np][0] = t0; bl[2 * np][1] = t1;
                bl[2 * np + 1][0] = t2; bl[2 * np + 1][1] = t3;
            }
#pragma unroll
            for (int mt = 0; mt < 2; mt++)
#pragma unroll
                for (int nt = 0; nt < 8; nt++) {
                    MMA16816(acc[mt][nt], ah[mt], bh[nt]);
                    MMA16816(acc[mt][nt], ah[mt], bl[nt]);
                    MMA16816(acc[mt][nt], al[mt], bh[nt]);
                }
        }
        __syncthreads();
    }

    const int er = lane >> 2;
    const int ec = (lane & 3) * 2;
#pragma unroll
    for (int mt = 0; mt < 2; mt++) {
#pragma unroll
        for (int nt = 0; nt < 8; nt++) {
            const int ct = wn + nt * 8 + ec;
            const int row0 = m0 + wm + mt * 16 + er;
            float x0 = acc[mt][nt][0] + sbias[ct];
            float x1 = acc[mt][nt][1] + sbias[ct + 1];
            float x2 = acc[mt][nt][2] + sbias[ct];
            float x3 = acc[mt][nt][3] + sbias[ct + 1];
            const size_t i0 = (size_t)row0 * DD + n0 + ct;
            const size_t i1 = (size_t)(row0 + 8) * DD + n0 + ct;
            if (splitout) {
                *(uint32_t*)&Ch[i0] = packbf(x0, x1);
                *(uint32_t*)&Cl[i0] = packbf(bflo(x0), bflo(x1));
                *(uint32_t*)&Ch[i1] = packbf(x2, x3);
                *(uint32_t*)&Cl[i1] = packbf(bflo(x2), bflo(x3));
            } else {
                float2 v0 = {x0, x1}, v1 = {x2, x3};
                *(float2*)&C[i0] = v0;
                *(float2*)&C[i1] = v1;
            }
        }
    }
}

// ===========================================================================
// mma.sync sliding-window flash attention, bf16x3, online softmax in regs.
// CTA = 128 queries x 1 head, 8 warps (16 q-rows each). 18 key tiles of 64.
// Scores/P never touch smem: C-layout of QK == A-layout for PV.
// Writes O as bf16 hi/lo (consumed by final GEMM).
// ===========================================================================
#define AOFF_QH 0
#define AOFF_QL 16384
#define AOFF_KH 32768
#define AOFF_KL 40960
#define AOFF_VH 49152
#define AOFF_VL 57344
#define ATT_SMEM 65536

__global__ __launch_bounds__(256, 2)
void attn_mma(const __nv_bfloat16* __restrict__ Qh,
              const __nv_bfloat16* __restrict__ Ql,
              const __nv_bfloat16* __restrict__ Kh,
              const __nv_bfloat16* __restrict__ Kl,
              const __nv_bfloat16* __restrict__ Vh,
              const __nv_bfloat16* __restrict__ Vl,
              __nv_bfloat16* __restrict__ Oh,
              __nv_bfloat16* __restrict__ Ol) {
    extern __shared__ char sm[];
    const uint32_t sbase = smem_u32(sm);

    const int tid = threadIdx.x;
    const int wid = tid >> 5, lane = tid & 31;
    const int qs = blockIdx.x * 128;
    const int hoff = blockIdx.y * HDIM;
    const int localr = lane & 7, sel = lane >> 3;

    // ---- stage Q tile (128 x 64 bf16 hi/lo), swizzled ----
    {
        const int r = tid >> 1;
        const int half = (tid & 1) * 32;   // bf16 cols
        const size_t g = (size_t)(qs + r) * DD + hoff + half;
#pragma unroll
        for (int j = 0; j < 4; j++) {
            uint32_t off = SWZ((uint32_t)(r * 128 + (half + 8 * j) * 2));
            *(uint4*)(sm + AOFF_QH + off) = *(const uint4*)&Qh[g + 8 * j];
            *(uint4*)(sm + AOFF_QL + off) = *(const uint4*)&Ql[g + 8 * j];
        }
    }

    const int q0 = qs + 16 * wid + (lane >> 2);   // row 0 abs
    const int q1 = q0 + 8;                        // row 1 abs

    float m0 = -1e30f, m1 = -1e30f, l0 = 0.f, l1 = 0.f;
    float oacc[8][4];
#pragma unroll
    for (int nt = 0; nt < 8; nt++)
#pragma unroll
        for (int e = 0; e < 4; e++) oacc[nt][e] = 0.f;

    for (int t = 0; t < 18; t++) {
        const int kt = qs - 512 + 64 * t;
        if (kt >= SS || kt + 64 <= 0) continue;

        // ---- stage K,V tiles (64 x 64 bf16 hi/lo), zero-fill OOB ----
        {
            const int r = tid >> 2;
            const int cw = (tid & 3) * 16;    // bf16 cols
            const int kabs = kt + r;
            if (kabs >= 0 && kabs < SS) {
                const size_t g = (size_t)kabs * DD + hoff + cw;
#pragma unroll
                for (int j = 0; j < 2; j++) {
                    uint32_t off = SWZ((uint32_t)(r * 128 + (cw + 8 * j) * 2));
                    *(uint4*)(sm + AOFF_KH + off) = *(const uint4*)&Kh[g + 8 * j];
                    *(uint4*)(sm + AOFF_KL + off) = *(const uint4*)&Kl[g + 8 * j];
                    *(uint4*)(sm + AOFF_VH + off) = *(const uint4*)&Vh[g + 8 * j];
                    *(uint4*)(sm + AOFF_VL + off) = *(const uint4*)&Vl[g + 8 * j];
                }
            } else {
                const uint4 z = {0, 0, 0, 0};
#pragma unroll
                for (int j = 0; j < 2; j++) {
                    uint32_t off = SWZ((uint32_t)(r * 128 + (cw + 8 * j) * 2));
                    *(uint4*)(sm + AOFF_KH + off) = z;
                    *(uint4*)(sm + AOFF_KL + off) = z;
                    *(uint4*)(sm + AOFF_VH + off) = z;
                    *(uint4*)(sm + AOFF_VL + off) = z;
                }
            }
        }
        __syncthreads();

        // ---- QK^T: S (16q x 64k per warp) ----
        float sacc[8][4];
#pragma unroll
        for (int nt = 0; nt < 8; nt++)
#pragma unroll
            for (int e = 0; e < 4; e++) sacc[nt][e] = 0.f;

#pragma unroll
        for (int kk = 0; kk < 64; kk += 16) {
            uint32_t qhf[4], qlf[4];
            {
                const int row = 16 * wid + localr + (sel & 1) * 8;
                const int kb = kk + (sel >> 1) * 8;
                const uint32_t off = SWZ((uint32_t)(row * 128 + kb * 2));
                LDSM_X4(qhf[0], qhf[1], qhf[2], qhf[3], sbase + AOFF_QH + off);
                LDSM_X4(qlf[0], qlf[1], qlf[2], qlf[3], sbase + AOFF_QL + off);
            }
            uint32_t khf[8][2], klf[8][2];
#pragma unroll
            for (int np = 0; np < 4; np++) {
                const int row = np * 16 + (sel >> 1) * 8 + localr;
                const int kb = kk + (sel & 1) * 8;
                const uint32_t off = SWZ((uint32_t)(row * 128 + kb * 2));
                uint32_t t0, t1, t2, t3;
                LDSM_X4(t0, t1, t2, t3, sbase + AOFF_KH + off);
                khf[2 * np][0] = t0; khf[2 * np][1] = t1;
                khf[2 * np + 1][0] = t2; khf[2 * np + 1][1] = t3;
                LDSM_X4(t0, t1, t2, t3, sbase + AOFF_KL + off);
                klf[2 * np][0] = t0; klf[2 * np][1] = t1;
                klf[2 * np + 1][0] = t2; klf[2 * np + 1][1] = t3;
            }
#pragma unroll
            for (int nt = 0; nt < 8; nt++) {
                MMA16816(sacc[nt], qhf, khf[nt]);
                MMA16816(sacc[nt], qhf, klf[nt]);
                MMA16816(sacc[nt], qlf, khf[nt]);
            }
        }

        // ---- mask + online softmax (registers) ----
        const int cb = kt + 2 * (lane & 3);
        float mx0 = -1e30f, mx1 = -1e30f;
#pragma unroll
        for (int nt = 0; nt < 8; nt++) {
#pragma unroll
            for (int e = 0; e < 2; e++) {
                const int kabs = cb + 8 * nt + e;
                const bool inb = (kabs >= 0) & (kabs < SS);
                float s0 = (inb & (kabs >= q0 - 512) & (kabs < q0 + 512))
                               ? sacc[nt][e] * 0.125f : -1e30f;
                float s1 = (inb & (kabs >= q1 - 512) & (kabs < q1 + 512))
                               ? sacc[nt][e + 2] * 0.125f : -1e30f;
                sacc[nt][e] = s0; sacc[nt][e + 2] = s1;
                mx0 = fmaxf(mx0, s0); mx1 = fmaxf(mx1, s1);
            }
        }
        mx0 = fmaxf(mx0, __shfl_xor_sync(0xffffffffu, mx0, 1));
        mx0 = fmaxf(mx0, __shfl_xor_sync(0xffffffffu, mx0, 2));
        mx1 = fmaxf(mx1, __shfl_xor_sync(0xffffffffu, mx1, 1));
        mx1 = fmaxf(mx1, __shfl_xor_sync(0xffffffffu, mx1, 2));
        const float mn0 = fmaxf(m0, mx0), mn1 = fmaxf(m1, mx1);
        const float a0 = __expf(m0 - mn0), a1 = __expf(m1 - mn1);
        m0 = mn0; m1 = mn1;
        float rs0 = 0.f, rs1 = 0.f;
#pragma unroll
        for (int nt = 0; nt < 8; nt++) {
#pragma unroll
            for (int e = 0; e < 2; e++) {
                float p0 = (sacc[nt][e] > -5e29f) ? __expf(sacc[nt][e] - mn0) : 0.f;
                float p1 = (sacc[nt][e + 2] > -5e29f) ? __expf(sacc[nt][e + 2] - mn1) : 0.f;
                rs0 += p0; rs1 += p1;
                sacc[nt][e] = p0; sacc[nt][e + 2] = p1;
            }
        }
        l0 = l0 * a0 + rs0;
        l1 = l1 * a1 + rs1;
#pragma unroll
        for (int nt = 0; nt < 8; nt++) {
            oacc[nt][0] *= a0; oacc[nt][1] *= a0;
            oacc[nt][2] *= a1; oacc[nt][3] *= a1;
        }

        // ---- PV: O += P * V ----
#pragma unroll
        for (int kc = 0; kc < 4; kc++) {
            uint32_t pah[4], pal[4];
            pah[0] = packbf(sacc[2 * kc][0], sacc[2 * kc][1]);
            pah[1] = packbf(sacc[2 * kc][2], sacc[2 * kc][3]);
            pah[2] = packbf(sacc[2 * kc + 1][0], sacc[2 * kc + 1][1]);
            pah[3] = packbf(sacc[2 * kc + 1][2], sacc[2 * kc + 1][3]);
            pal[0] = packbf(bflo(sacc[2 * kc][0]), bflo(sacc[2 * kc][1]));
            pal[1] = packbf(bflo(sacc[2 * kc][2]), bflo(sacc[2 * kc][3]));
            pal[2] = packbf(bflo(sacc[2 * kc + 1][0]), bflo(sacc[2 * kc + 1][1]));
            pal[3] = packbf(bflo(sacc[2 * kc + 1][2]), bflo(sacc[2 * kc + 1][3]));

            uint32_t vhf[8][2], vlf[8][2];
#pragma unroll
            for (int ntp = 0; ntp < 4; ntp++) {
                const int key = 16 * kc + (sel & 1) * 8 + localr;
                const int dim = (2 * ntp + (sel >> 1)) * 8;
                const uint32_t off = SWZ((uint32_t)(key * 128 + dim * 2));
                uint32_t t0, t1, t2, t3;
                LDSM_X4_T(t0, t1, t2, t3, sbase + AOFF_VH + off);
                vhf[2 * ntp][0] = t0; vhf[2 * ntp][1] = t1;
                vhf[2 * ntp + 1][0] = t2; vhf[2 * ntp + 1][1] = t3;
                LDSM_X4_T(t0, t1, t2, t3, sbase + AOFF_VL + off);
                vlf[2 * ntp][0] = t0; vlf[2 * ntp][1] = t1;
                vlf[2 * ntp + 1][0] = t2; vlf[2 * ntp + 1][1] = t3;
            }
#pragma unroll
            for (int nt = 0; nt < 8; nt++) {
                MMA16816(oacc[nt], pah, vhf[nt]);
                MMA16816(oacc[nt], pah, vlf[nt]);
                MMA16816(oacc[nt], pal, vhf[nt]);
            }
        }
        __syncthreads();
    }

    // ---- epilogue: normalize, blend weight, write bf16 hi/lo ----
    l0 += __shfl_xor_sync(0xffffffffu, l0, 1);
    l0 += __shfl_xor_sync(0xffffffffu, l0, 2);
    l1 += __shfl_xor_sync(0xffffffffu, l1, 1);
    l1 += __shfl_xor_sync(0xffffffffu, l1, 2);
    float w0 = 1.f, w1 = 1.f;
    if (q0 >= SS - 128) w0 = 1.f + (float)(q0 - (SS - 128)) * (1.f / 127.f);
    if (q1 >= SS - 128) w1 = 1.f + (float)(q1 - (SS - 128)) * (1.f / 127.f);
    const float sc0 = w0 / l0, sc1 = w1 / l1;
    const int ec = 2 * (lane & 3);
#pragma unroll
    for (int nt = 0; nt < 8; nt++) {
        const size_t i0 = (size_t)q0 * DD + hoff + 8 * nt + ec;
        const size_t i1 = (size_t)q1 * DD + hoff + 8 * nt + ec;
        float x0 = oacc[nt][0] * sc0, x1 = oacc[nt][1] * sc0;
        float x2 = oacc[nt][2] * sc1, x3 = oacc[nt][3] * sc1;
        *(uint32_t*)&Oh[i0] = packbf(x0, x1);
        *(uint32_t*)&Ol[i0] = packbf(bflo(x0), bflo(x1));
        *(uint32_t*)&Oh[i1] = packbf(x2, x3);
        *(uint32_t*)&Ol[i1] = packbf(bflo(x2), bflo(x3));
    }
}

// ===========================================================================
extern "C" void kernel_launch(void* const* d_in, const int* in_sizes, int n_in,
                              void* d_out, int out_size) {
    const float* x = nullptr;
    const float* Wm[4] = {nullptr, nullptr, nullptr, nullptr};
    const float* bm[4] = {nullptr, nullptr, nullptr, nullptr};
    int nw = 0, nb = 0;
    for (int i = 0; i < n_in; i++) {
        const float* p = (const float*)d_in[i];
        if (in_sizes[i] == SS * DD) x = p;
        else if (in_sizes[i] == DD * DD) { if (nw < 4) Wm[nw++] = p; }
        else if (in_sizes[i] == DD) { if (nb < 4) bm[nb++] = p; }
    }
    float* out = (float*)d_out;

    __nv_bfloat16 *xh, *xl, *Wh, *Wl, *Qh, *Ql, *Kh, *Kl, *Vh, *Vl, *Oh, *Ol;
    cudaGetSymbolAddress((void**)&xh, g_xh);
    cudaGetSymbolAddress((void**)&xl, g_xl);
    cudaGetSymbolAddress((void**)&Wh, g_Wh);
    cudaGetSymbolAddress((void**)&Wl, g_Wl);
    cudaGetSymbolAddress((void**)&Qh, g_Qh);
    cudaGetSymbolAddress((void**)&Ql, g_Ql);
    cudaGetSymbolAddress((void**)&Kh, g_Kh);
    cudaGetSymbolAddress((void**)&Kl, g_Kl);
    cudaGetSymbolAddress((void**)&Vh, g_Vh);
    cudaGetSymbolAddress((void**)&Vl, g_Vl);
    cudaGetSymbolAddress((void**)&Oh, g_Oh);
    cudaGetSymbolAddress((void**)&Ol, g_Ol);

    // ---- split inputs to bf16 hi/lo ----
    split_k<<<(SS * DD / 8 + 255) / 256, 256>>>(x, xh, xl, SS * DD / 8);
    for (int w = 0; w < 4; w++)
        split_k<<<(DD * DD / 8 + 255) / 256, 256>>>(
            Wm[w], Wh + (size_t)w * DD * DD, Wl + (size_t)w * DD * DD,
            DD * DD / 8);

    cudaFuncSetAttribute(gemm_mma, cudaFuncAttributeMaxDynamicSharedMemorySize,
                         GEMM_SMEM);
    cudaFuncSetAttribute(attn_mma, cudaFuncAttributeMaxDynamicSharedMemorySize,
                         ATT_SMEM);

    dim3 ggrid(DD / 128, SS / 128);
    gemm_mma<<<ggrid, 256, GEMM_SMEM>>>(xh, xl, Wh, Wl, bm[0],
                                        nullptr, Qh, Ql, 1);
    gemm_mma<<<ggrid, 256, GEMM_SMEM>>>(xh, xl, Wh + (size_t)1 * DD * DD,
                                        Wl + (size_t)1 * DD * DD, bm[1],
                                        nullptr, Kh, Kl, 1);
    gemm_mma<<<ggrid, 256, GEMM_SMEM>>>(xh, xl, Wh + (size_t)2 * DD * DD,
                                        Wl + (size_t)2 * DD * DD, bm[2],
                                        nullptr, Vh, Vl, 1);

    attn_mma<<<dim3(SS / 128, HH), 256, ATT_SMEM>>>(Qh, Ql, Kh, Kl, Vh, Vl,
                                                    Oh, Ol);

    gemm_mma<<<ggrid, 256, GEMM_SMEM>>>(Oh, Ol, Wh + (size_t)3 * DD * DD,
                                        Wl + (size_t)3 * DD * DD, bm[3],
                                        out, nullptr, nullptr, 0);
}

// round 8
// speedup vs baseline: 2.2419x; 1.1548x over previous
#include <cuda_runtime.h>
#include <cuda_bf16.h>
#include <stdint.h>
#include <math.h>

#define SS 8192
#define DD 1024
#define HH 16
#define HDIM 64

// ---- scratch: bf16 hi/lo pairs (static device arrays) ----
__device__ __nv_bfloat16 g_xh[SS * DD], g_xl[SS * DD];
__device__ __nv_bfloat16 g_Wh[4][DD * DD], g_Wl[4][DD * DD];
__device__ __nv_bfloat16 g_Qh[SS * DD], g_Ql[SS * DD];
__device__ __nv_bfloat16 g_Kh[SS * DD], g_Kl[SS * DD];
__device__ __nv_bfloat16 g_Vh[SS * DD], g_Vl[SS * DD];
__device__ __nv_bfloat16 g_Oh[SS * DD], g_Ol[SS * DD];

// ===========================================================================
// PTX helpers (baseline ISA: ldmatrix + mma.sync + cp.async, sm_80+)
// ===========================================================================
__device__ __forceinline__ uint32_t smem_u32(const void* p) {
    uint32_t a;
    asm("{ .reg .u64 t; cvta.to.shared.u64 t, %1; cvt.u32.u64 %0, t; }"
        : "=r"(a) : "l"(p));
    return a;
}

#define LDSM_X4(r0, r1, r2, r3, addr)                                       \
    asm volatile(                                                           \
        "ldmatrix.sync.aligned.m8n8.x4.shared.b16 {%0, %1, %2, %3}, [%4];"  \
        : "=r"(r0), "=r"(r1), "=r"(r2), "=r"(r3) : "r"(addr))

#define LDSM_X4_T(r0, r1, r2, r3, addr)                                     \
    asm volatile(                                                           \
        "ldmatrix.sync.aligned.m8n8.x4.trans.shared.b16 {%0, %1, %2, %3}, [%4];" \
        : "=r"(r0), "=r"(r1), "=r"(r2), "=r"(r3) : "r"(addr))

#define MMA16816(d, a, b)                                                   \
    asm volatile(                                                           \
        "mma.sync.aligned.m16n8k16.row.col.f32.bf16.bf16.f32 "              \
        "{%0, %1, %2, %3}, {%4, %5, %6, %7}, {%8, %9}, {%0, %1, %2, %3};"   \
        : "+f"((d)[0]), "+f"((d)[1]), "+f"((d)[2]), "+f"((d)[3])            \
        : "r"((a)[0]), "r"((a)[1]), "r"((a)[2]), "r"((a)[3]),               \
          "r"((b)[0]), "r"((b)[1]))

#define CPA16(dst, src, sz)                                                 \
    asm volatile("cp.async.cg.shared.global [%0], [%1], 16, %2;"            \
                 :: "r"(dst), "l"(src), "r"(sz))
#define CPA_COMMIT() asm volatile("cp.async.commit_group;" ::: "memory")
#define CPA_WAIT1()  asm volatile("cp.async.wait_group 1;" ::: "memory")
#define CPA_WAIT0()  asm volatile("cp.async.wait_group 0;" ::: "memory")

#define SWZ(o) ((o) ^ (((o) >> 3) & 0x70))

__device__ __forceinline__ uint32_t packbf(float x, float y) {
    __nv_bfloat162 t;
    t.x = __float2bfloat16(x);
    t.y = __float2bfloat16(y);
    return *(uint32_t*)&t;
}
__device__ __forceinline__ float bflo(float x) {
    return x - __bfloat162float(__float2bfloat16(x));
}

// ===========================================================================
// fp32 -> bf16 hi/lo split (one pass, vectorized x8)
// ===========================================================================
__global__ void split_k(const float* __restrict__ in,
                        __nv_bfloat16* __restrict__ hi,
                        __nv_bfloat16* __restrict__ lo, int n8) {
    int i = blockIdx.x * blockDim.x + threadIdx.x;
    if (i >= n8) return;
    const float4* p = (const float4*)in + (size_t)i * 2;
    float4 v0 = p[0], v1 = p[1];
    float v[8] = {v0.x, v0.y, v0.z, v0.w, v1.x, v1.y, v1.z, v1.w};
    __nv_bfloat16 h[8], l[8];
#pragma unroll
    for (int j = 0; j < 8; j++) {
        h[j] = __float2bfloat16(v[j]);
        l[j] = __float2bfloat16(v[j] - __bfloat162float(h[j]));
    }
    ((uint4*)hi)[i] = *(uint4*)h;
    ((uint4*)lo)[i] = *(uint4*)l;
}

// ===========================================================================
// mma.sync GEMM, bf16x3 emulated-fp32, 2-stage cp.async pipeline:
//   C[m,n] = sum_k A[m,k]*W[n,k] + bias[n]
// CTA 128x128, K-chunk 64, 256 threads (8 warps of 32m x 64n).
// smem: bias 512B @0; stage s @ 1024 + s*65536 {AH,AL,BH,BL} x 16KB.
// ===========================================================================
#define G_ST(s)  (1024 + (s) * 65536)
#define G_AH 0
#define G_AL 16384
#define G_BH 32768
#define G_BL 49152
#define GEMM_SMEM (1024 + 2 * 65536)
#define NCHUNK 16

__global__ __launch_bounds__(256)
void gemm_mma(const __nv_bfloat16* __restrict__ Ah,
              const __nv_bfloat16* __restrict__ Al,
              const __nv_bfloat16* __restrict__ Bh,
              const __nv_bfloat16* __restrict__ Bl,
              const float* __restrict__ bias,
              float* __restrict__ C,
              __nv_bfloat16* __restrict__ Ch,
              __nv_bfloat16* __restrict__ Cl,
              int splitout) {
    extern __shared__ char sm[];
    const uint32_t sbase = smem_u32(sm);
    float* sbias = (float*)sm;

    const int tid = threadIdx.x;
    const int wid = tid >> 5, lane = tid & 31;
    const int n0 = blockIdx.x * 128, m0 = blockIdx.y * 128;

    if (tid < 128) sbias[tid] = bias[n0 + tid];

    const int wm = (wid & 3) * 32;
    const int wn = (wid >> 2) * 64;

    float acc[2][8][4];
#pragma unroll
    for (int mt = 0; mt < 2; mt++)
#pragma unroll
        for (int nt = 0; nt < 8; nt++)
#pragma unroll
            for (int e = 0; e < 4; e++) acc[mt][nt][e] = 0.f;

    const int cr = tid >> 1;
    const int hc = (tid & 1) * 32;   // bf16 elements
    const int localr = lane & 7, sel = lane >> 3;

    const __nv_bfloat16* rowA_h = Ah + (size_t)(m0 + cr) * DD + hc;
    const __nv_bfloat16* rowA_l = Al + (size_t)(m0 + cr) * DD + hc;
    const __nv_bfloat16* rowB_h = Bh + (size_t)(n0 + cr) * DD + hc;
    const __nv_bfloat16* rowB_l = Bl + (size_t)(n0 + cr) * DD + hc;

    // stage chunk c into stage s
#define G_STAGE(c, s)                                                       \
    do {                                                                    \
        const uint32_t stb = sbase + G_ST(s);                               \
        _Pragma("unroll")                                                   \
        for (int j = 0; j < 4; j++) {                                       \
            uint32_t off = SWZ((uint32_t)(cr * 128 + (hc + 8 * j) * 2));    \
            CPA16(stb + G_AH + off, rowA_h + (c) * 64 + 8 * j, 16);         \
            CPA16(stb + G_AL + off, rowA_l + (c) * 64 + 8 * j, 16);         \
            CPA16(stb + G_BH + off, rowB_h + (c) * 64 + 8 * j, 16);         \
            CPA16(stb + G_BL + off, rowB_l + (c) * 64 + 8 * j, 16);         \
        }                                                                   \
        CPA_COMMIT();                                                       \
    } while (0)

    G_STAGE(0, 0);

    for (int c = 0; c < NCHUNK; c++) {
        const int s = c & 1;
        if (c + 1 < NCHUNK) {
            G_STAGE(c + 1, s ^ 1);
            CPA_WAIT1();
        } else {
            CPA_WAIT0();
        }
        __syncthreads();

        const uint32_t stb = sbase + G_ST(s);
#pragma unroll
        for (int kk = 0; kk < 64; kk += 16) {
            uint32_t ah[2][4], al[2][4];
#pragma unroll
            for (int mt = 0; mt < 2; mt++) {
                const int row = wm + mt * 16 + localr + (sel & 1) * 8;
                const int kb = kk + (sel >> 1) * 8;
                const uint32_t off = SWZ((uint32_t)(row * 128 + kb * 2));
                LDSM_X4(ah[mt][0], ah[mt][1], ah[mt][2], ah[mt][3],
                        stb + G_AH + off);
                LDSM_X4(al[mt][0], al[mt][1], al[mt][2], al[mt][3],
                        stb + G_AL + off);
            }
            uint32_t bh[8][2], bl[8][2];
#pragma unroll
            for (int np = 0; np < 4; np++) {
                const int row = wn + np * 16 + (sel >> 1) * 8 + localr;
                const int kb = kk + (sel & 1) * 8;
                const uint32_t off = SWZ((uint32_t)(row * 128 + kb * 2));
                uint32_t t0, t1, t2, t3;
                LDSM_X4(t0, t1, t2, t3, stb + G_BH + off);
                bh[2 * np][0] = t0; bh[2 * np][1] = t1;
                bh[2 * np + 1][0] = t2; bh[2 * np + 1][1] = t3;
                LDSM_X4(t0, t1, t2, t3, stb + G_BL + off);
                bl[2 * np][0] = t0; bl[2 * np][1] = t1;
                bl[2 * np + 1][0] = t2; bl[2 * np + 1][1] = t3;
            }
#pragma unroll
            for (int mt = 0; mt < 2; mt++)
#pragma unroll
                for (int nt = 0; nt < 8; nt++) {
                    MMA16816(acc[mt][nt], ah[mt], bh[nt]);
                    MMA16816(acc[mt][nt], ah[mt], bl[nt]);
                    MMA16816(acc[mt][nt], al[mt], bh[nt]);
                }
        }
        __syncthreads();
    }

    const int er = lane >> 2;
    const int ec = (lane & 3) * 2;
#pragma unroll
    for (int mt = 0; mt < 2; mt++) {
#pragma unroll
        for (int nt = 0; nt < 8; nt++) {
            const int ct = wn + nt * 8 + ec;
            const int row0 = m0 + wm + mt * 16 + er;
            float x0 = acc[mt][nt][0] + sbias[ct];
            float x1 = acc[mt][nt][1] + sbias[ct + 1];
            float x2 = acc[mt][nt][2] + sbias[ct];
            float x3 = acc[mt][nt][3] + sbias[ct + 1];
            const size_t i0 = (size_t)row0 * DD + n0 + ct;
            const size_t i1 = (size_t)(row0 + 8) * DD + n0 + ct;
            if (splitout) {
                *(uint32_t*)&Ch[i0] = packbf(x0, x1);
                *(uint32_t*)&Cl[i0] = packbf(bflo(x0), bflo(x1));
                *(uint32_t*)&Ch[i1] = packbf(x2, x3);
                *(uint32_t*)&Cl[i1] = packbf(bflo(x2), bflo(x3));
            } else {
                float2 v0 = {x0, x1}, v1 = {x2, x3};
                *(float2*)&C[i0] = v0;
                *(float2*)&C[i1] = v1;
            }
        }
    }
}

// ===========================================================================
// mma.sync sliding-window flash attention, bf16x3, 2-stage cp.async K/V
// pipeline, online softmax in registers.
// CTA = 128 queries x 1 head, 8 warps (16 q-rows each).
// smem: Q hi/lo 32KB @0; K/V stage s @ 32768 + s*32768 {KH,KL,VH,VL} x 8KB.
// ===========================================================================
#define A_QH 0
#define A_QL 16384
#define A_ST(s) (32768 + (s) * 32768)
#define A_KH 0
#define A_KL 8192
#define A_VH 16384
#define A_VL 24576
#define ATT_SMEM (32768 + 2 * 32768)

__global__ __launch_bounds__(256, 2)
void attn_mma(const __nv_bfloat16* __restrict__ Qh,
              const __nv_bfloat16* __restrict__ Ql,
              const __nv_bfloat16* __restrict__ Kh,
              const __nv_bfloat16* __restrict__ Kl,
              const __nv_bfloat16* __restrict__ Vh,
              const __nv_bfloat16* __restrict__ Vl,
              __nv_bfloat16* __restrict__ Oh,
              __nv_bfloat16* __restrict__ Ol) {
    extern __shared__ char sm[];
    const uint32_t sbase = smem_u32(sm);

    const int tid = threadIdx.x;
    const int wid = tid >> 5, lane = tid & 31;
    const int qs = blockIdx.x * 128;
    const int hoff = blockIdx.y * HDIM;
    const int localr = lane & 7, sel = lane >> 3;

    // ---- stage Q tile (128 x 64 bf16 hi/lo), swizzled ----
    {
        const int r = tid >> 1;
        const int half = (tid & 1) * 32;   // bf16 cols
        const size_t g = (size_t)(qs + r) * DD + hoff + half;
#pragma unroll
        for (int j = 0; j < 4; j++) {
            uint32_t off = SWZ((uint32_t)(r * 128 + (half + 8 * j) * 2));
            *(uint4*)(sm + A_QH + off) = *(const uint4*)&Qh[g + 8 * j];
            *(uint4*)(sm + A_QL + off) = *(const uint4*)&Ql[g + 8 * j];
        }
    }

    // valid tile range: kt = qs - 512 + 64t, need kt+64 > 0 and kt < SS
    const int t0v = max(0, (512 - qs + 63) / 64);
    const int t1v = min(18, (SS + 512 - qs) / 64);

    // KV staging assignment
    const int svr = tid >> 2;            // 0..63
    const int svc = (tid & 3) * 16;      // bf16 cols

#define A_STAGE(t, s)                                                       \
    do {                                                                    \
        const int kt_ = qs - 512 + 64 * (t);                                \
        const int kabs_ = kt_ + svr;                                        \
        const bool inb_ = (kabs_ >= 0) && (kabs_ < SS);                     \
        const int kc_ = inb_ ? kabs_ : 0;                                   \
        const uint32_t sz_ = inb_ ? 16u : 0u;                               \
        const size_t g_ = (size_t)kc_ * DD + hoff + svc;                    \
        const uint32_t stb_ = sbase + A_ST(s);                              \
        _Pragma("unroll")                                                   \
        for (int j = 0; j < 2; j++) {                                       \
            uint32_t off = SWZ((uint32_t)(svr * 128 + (svc + 8 * j) * 2));  \
            CPA16(stb_ + A_KH + off, &Kh[g_ + 8 * j], sz_);                 \
            CPA16(stb_ + A_KL + off, &Kl[g_ + 8 * j], sz_);                 \
            CPA16(stb_ + A_VH + off, &Vh[g_ + 8 * j], sz_);                 \
            CPA16(stb_ + A_VL + off, &Vl[g_ + 8 * j], sz_);                 \
        }                                                                   \
        CPA_COMMIT();                                                       \
    } while (0)

    const int q0 = qs + 16 * wid + (lane >> 2);
    const int q1 = q0 + 8;

    float m0 = -1e30f, m1 = -1e30f, l0 = 0.f, l1 = 0.f;
    float oacc[8][4];
#pragma unroll
    for (int nt = 0; nt < 8; nt++)
#pragma unroll
        for (int e = 0; e < 4; e++) oacc[nt][e] = 0.f;

    A_STAGE(t0v, 0);

    for (int t = t0v; t < t1v; t++) {
        const int s = (t - t0v) & 1;
        const int kt = qs - 512 + 64 * t;
        if (t + 1 < t1v) {
            A_STAGE(t + 1, s ^ 1);
            CPA_WAIT1();
        } else {
            CPA_WAIT0();
        }
        __syncthreads();

        const uint32_t stb = sbase + A_ST(s);

        // ---- QK^T: S (16q x 64k per warp) ----
        float sacc[8][4];
#pragma unroll
        for (int nt = 0; nt < 8; nt++)
#pragma unroll
            for (int e = 0; e < 4; e++) sacc[nt][e] = 0.f;

#pragma unroll
        for (int kk = 0; kk < 64; kk += 16) {
            uint32_t qhf[4], qlf[4];
            {
                const int row = 16 * wid + localr + (sel & 1) * 8;
                const int kb = kk + (sel >> 1) * 8;
                const uint32_t off = SWZ((uint32_t)(row * 128 + kb * 2));
                LDSM_X4(qhf[0], qhf[1], qhf[2], qhf[3], sbase + A_QH + off);
                LDSM_X4(qlf[0], qlf[1], qlf[2], qlf[3], sbase + A_QL + off);
            }
            uint32_t khf[8][2], klf[8][2];
#pragma unroll
            for (int np = 0; np < 4; np++) {
                const int row = np * 16 + (sel >> 1) * 8 + localr;
                const int kb = kk + (sel & 1) * 8;
                const uint32_t off = SWZ((uint32_t)(row * 128 + kb * 2));
                uint32_t t0r, t1r, t2r, t3r;
                LDSM_X4(t0r, t1r, t2r, t3r, stb + A_KH + off);
                khf[2 * np][0] = t0r; khf[2 * np][1] = t1r;
                khf[2 * np + 1][0] = t2r; khf[2 * np + 1][1] = t3r;
                LDSM_X4(t0r, t1r, t2r, t3r, stb + A_KL + off);
                klf[2 * np][0] = t0r; klf[2 * np][1] = t1r;
                klf[2 * np + 1][0] = t2r; klf[2 * np + 1][1] = t3r;
            }
#pragma unroll
            for (int nt = 0; nt < 8; nt++) {
                MMA16816(sacc[nt], qhf, khf[nt]);
                MMA16816(sacc[nt], qhf, klf[nt]);
                MMA16816(sacc[nt], qlf, khf[nt]);
            }
        }

        // ---- mask + online softmax (registers) ----
        const int cb = kt + 2 * (lane & 3);
        float mx0 = -1e30f, mx1 = -1e30f;
#pragma unroll
        for (int nt = 0; nt < 8; nt++) {
#pragma unroll
            for (int e = 0; e < 2; e++) {
                const int kabs = cb + 8 * nt + e;
                const bool inb = (kabs >= 0) & (kabs < SS);
                float s0 = (inb & (kabs >= q0 - 512) & (kabs < q0 + 512))
                               ? sacc[nt][e] * 0.125f : -1e30f;
                float s1 = (inb & (kabs >= q1 - 512) & (kabs < q1 + 512))
                               ? sacc[nt][e + 2] * 0.125f : -1e30f;
                sacc[nt][e] = s0; sacc[nt][e + 2] = s1;
                mx0 = fmaxf(mx0, s0); mx1 = fmaxf(mx1, s1);
            }
        }
        mx0 = fmaxf(mx0, __shfl_xor_sync(0xffffffffu, mx0, 1));
        mx0 = fmaxf(mx0, __shfl_xor_sync(0xffffffffu, mx0, 2));
        mx1 = fmaxf(mx1, __shfl_xor_sync(0xffffffffu, mx1, 1));
        mx1 = fmaxf(mx1, __shfl_xor_sync(0xffffffffu, mx1, 2));
        const float mn0 = fmaxf(m0, mx0), mn1 = fmaxf(m1, mx1);
        const float a0 = __expf(m0 - mn0), a1 = __expf(m1 - mn1);
        m0 = mn0; m1 = mn1;
        float rs0 = 0.f, rs1 = 0.f;
#pragma unroll
        for (int nt = 0; nt < 8; nt++) {
#pragma unroll
            for (int e = 0; e < 2; e++) {
                float p0 = (sacc[nt][e] > -5e29f) ? __expf(sacc[nt][e] - mn0) : 0.f;
                float p1 = (sacc[nt][e + 2] > -5e29f) ? __expf(sacc[nt][e + 2] - mn1) : 0.f;
                rs0 += p0; rs1 += p1;
                sacc[nt][e] = p0; sacc[nt][e + 2] = p1;
            }
        }
        l0 = l0 * a0 + rs0;
        l1 = l1 * a1 + rs1;
#pragma unroll
        for (int nt = 0; nt < 8; nt++) {
            oacc[nt][0] *= a0; oacc[nt][1] *= a0;
            oacc[nt][2] *= a1; oacc[nt][3] *= a1;
        }

        // ---- PV: O += P * V ----
#pragma unroll
        for (int kc = 0; kc < 4; kc++) {
            uint32_t pah[4], pal[4];
            pah[0] = packbf(sacc[2 * kc][0], sacc[2 * kc][1]);
            pah[1] = packbf(sacc[2 * kc][2], sacc[2 * kc][3]);
            pah[2] = packbf(sacc[2 * kc + 1][0], sacc[2 * kc + 1][1]);
            pah[3] = packbf(sacc[2 * kc + 1][2], sacc[2 * kc + 1][3]);
            pal[0] = packbf(bflo(sacc[2 * kc][0]), bflo(sacc[2 * kc][1]));
            pal[1] = packbf(bflo(sacc[2 * kc][2]), bflo(sacc[2 * kc][3]));
            pal[2] = packbf(bflo(sacc[2 * kc + 1][0]), bflo(sacc[2 * kc + 1][1]));
            pal[3] = packbf(bflo(sacc[2 * kc + 1][2]), bflo(sacc[2 * kc + 1][3]));

            uint32_t vhf[8][2], vlf[8][2];
#pragma unroll
            for (int ntp = 0; ntp < 4; ntp++) {
                const int key = 16 * kc + (sel & 1) * 8 + localr;
                const int dim = (2 * ntp + (sel >> 1)) * 8;
                const uint32_t off = SWZ((uint32_t)(key * 128 + dim * 2));
                uint32_t t0r, t1r, t2r, t3r;
                LDSM_X4_T(t0r, t1r, t2r, t3r, stb + A_VH + off);
                vhf[2 * ntp][0] = t0r; vhf[2 * ntp][1] = t1r;
                vhf[2 * ntp + 1][0] = t2r; vhf[2 * ntp + 1][1] = t3r;
                LDSM_X4_T(t0r, t1r, t2r, t3r, stb + A_VL + off);
                vlf[2 * ntp][0] = t0r; vlf[2 * ntp][1] = t1r;
                vlf[2 * ntp + 1][0] = t2r; vlf[2 * ntp + 1][1] = t3r;
            }
#pragma unroll
            for (int nt = 0; nt < 8; nt++) {
                MMA16816(oacc[nt], pah, vhf[nt]);
                MMA16816(oacc[nt], pah, vlf[nt]);
                MMA16816(oacc[nt], pal, vhf[nt]);
            }
        }
        __syncthreads();
    }

    // ---- epilogue: normalize, blend weight, write bf16 hi/lo ----
    l0 += __shfl_xor_sync(0xffffffffu, l0, 1);
    l0 += __shfl_xor_sync(0xffffffffu, l0, 2);
    l1 += __shfl_xor_sync(0xffffffffu, l1, 1);
    l1 += __shfl_xor_sync(0xffffffffu, l1, 2);
    float w0 = 1.f, w1 = 1.f;
    if (q0 >= SS - 128) w0 = 1.f + (float)(q0 - (SS - 128)) * (1.f / 127.f);
    if (q1 >= SS - 128) w1 = 1.f + (float)(q1 - (SS - 128)) * (1.f / 127.f);
    const float sc0 = w0 / l0, sc1 = w1 / l1;
    const int ec = 2 * (lane & 3);
#pragma unroll
    for (int nt = 0; nt < 8; nt++) {
        const size_t i0 = (size_t)q0 * DD + hoff + 8 * nt + ec;
        const size_t i1 = (size_t)q1 * DD + hoff + 8 * nt + ec;
        float x0 = oacc[nt][0] * sc0, x1 = oacc[nt][1] * sc0;
        float x2 = oacc[nt][2] * sc1, x3 = oacc[nt][3] * sc1;
        *(uint32_t*)&Oh[i0] = packbf(x0, x1);
        *(uint32_t*)&Ol[i0] = packbf(bflo(x0), bflo(x1));
        *(uint32_t*)&Oh[i1] = packbf(x2, x3);
        *(uint32_t*)&Ol[i1] = packbf(bflo(x2), bflo(x3));
    }
}

// ===========================================================================
extern "C" void kernel_launch(void* const* d_in, const int* in_sizes, int n_in,
                              void* d_out, int out_size) {
    const float* x = nullptr;
    const float* Wm[4] = {nullptr, nullptr, nullptr, nullptr};
    const float* bm[4] = {nullptr, nullptr, nullptr, nullptr};
    int nw = 0, nb = 0;
    for (int i = 0; i < n_in; i++) {
        const float* p = (const float*)d_in[i];
        if (in_sizes[i] == SS * DD) x = p;
        else if (in_sizes[i] == DD * DD) { if (nw < 4) Wm[nw++] = p; }
        else if (in_sizes[i] == DD) { if (nb < 4) bm[nb++] = p; }
    }
    float* out = (float*)d_out;

    __nv_bfloat16 *xh, *xl, *Wh, *Wl, *Qh, *Ql, *Kh, *Kl, *Vh, *Vl, *Oh, *Ol;
    cudaGetSymbolAddress((void**)&xh, g_xh);
    cudaGetSymbolAddress((void**)&xl, g_xl);
    cudaGetSymbolAddress((void**)&Wh, g_Wh);
    cudaGetSymbolAddress((void**)&Wl, g_Wl);
    cudaGetSymbolAddress((void**)&Qh, g_Qh);
    cudaGetSymbolAddress((void**)&Ql, g_Ql);
    cudaGetSymbolAddress((void**)&Kh, g_Kh);
    cudaGetSymbolAddress((void**)&Kl, g_Kl);
    cudaGetSymbolAddress((void**)&Vh, g_Vh);
    cudaGetSymbolAddress((void**)&Vl, g_Vl);
    cudaGetSymbolAddress((void**)&Oh, g_Oh);
    cudaGetSymbolAddress((void**)&Ol, g_Ol);

    // ---- split inputs to bf16 hi/lo ----
    split_k<<<(SS * DD / 8 + 255) / 256, 256>>>(x, xh, xl, SS * DD / 8);
    for (int w = 0; w < 4; w++)
        split_k<<<(DD * DD / 8 + 255) / 256, 256>>>(
            Wm[w], Wh + (size_t)w * DD * DD, Wl + (size_t)w * DD * DD,
            DD * DD / 8);

    cudaFuncSetAttribute(gemm_mma, cudaFuncAttributeMaxDynamicSharedMemorySize,
                         GEMM_SMEM);
    cudaFuncSetAttribute(attn_mma, cudaFuncAttributeMaxDynamicSharedMemorySize,
                         ATT_SMEM);

    dim3 ggrid(DD / 128, SS / 128);
    gemm_mma<<<ggrid, 256, GEMM_SMEM>>>(xh, xl, Wh, Wl, bm[0],
                                        nullptr, Qh, Ql, 1);
    gemm_mma<<<ggrid, 256, GEMM_SMEM>>>(xh, xl, Wh + (size_t)1 * DD * DD,
                                        Wl + (size_t)1 * DD * DD, bm[1],
                                        nullptr, Kh, Kl, 1);
    gemm_mma<<<ggrid, 256, GEMM_SMEM>>>(xh, xl, Wh + (size_t)2 * DD * DD,
                                        Wl + (size_t)2 * DD * DD, bm[2],
                                        nullptr, Vh, Vl, 1);

    attn_mma<<<dim3(SS / 128, HH), 256, ATT_SMEM>>>(Qh, Ql, Kh, Kl, Vh, Vl,
                                                    Oh, Ol);

    gemm_mma<<<ggrid, 256, GEMM_SMEM>>>(Oh, Ol, Wh + (size_t)3 * DD * DD,
                                        Wl + (size_t)3 * DD * DD, bm[3],
                                        out, nullptr, nullptr, 0);
}

// round 9
// speedup vs baseline: 2.5382x; 1.1322x over previous
#include <cuda_runtime.h>
#include <cuda_bf16.h>
#include <stdint.h>
#include <math.h>

#define SS 8192
#define DD 1024
#define HH 16
#define HDIM 64

// ---- scratch: bf16 hi/lo pairs (static device arrays) ----
__device__ __nv_bfloat16 g_xh[SS * DD], g_xl[SS * DD];
__device__ __nv_bfloat16 g_Wh[4][DD * DD], g_Wl[4][DD * DD];
__device__ __nv_bfloat16 g_Qh[SS * DD], g_Ql[SS * DD];
__device__ __nv_bfloat16 g_Kh[SS * DD], g_Kl[SS * DD];
__device__ __nv_bfloat16 g_Vh[SS * DD], g_Vl[SS * DD];
__device__ __nv_bfloat16 g_Oh[SS * DD], g_Ol[SS * DD];

// ===========================================================================
// PTX helpers (baseline ISA: ldmatrix + mma.sync + cp.async, sm_80+)
// ===========================================================================
__device__ __forceinline__ uint32_t smem_u32(const void* p) {
    uint32_t a;
    asm("{ .reg .u64 t; cvta.to.shared.u64 t, %1; cvt.u32.u64 %0, t; }"
        : "=r"(a) : "l"(p));
    return a;
}

#define LDSM_X4(r0, r1, r2, r3, addr)                                       \
    asm volatile(                                                           \
        "ldmatrix.sync.aligned.m8n8.x4.shared.b16 {%0, %1, %2, %3}, [%4];"  \
        : "=r"(r0), "=r"(r1), "=r"(r2), "=r"(r3) : "r"(addr))

#define LDSM_X4_T(r0, r1, r2, r3, addr)                                     \
    asm volatile(                                                           \
        "ldmatrix.sync.aligned.m8n8.x4.trans.shared.b16 {%0, %1, %2, %3}, [%4];" \
        : "=r"(r0), "=r"(r1), "=r"(r2), "=r"(r3) : "r"(addr))

#define MMA16816(d, a, b)                                                   \
    asm volatile(                                                           \
        "mma.sync.aligned.m16n8k16.row.col.f32.bf16.bf16.f32 "              \
        "{%0, %1, %2, %3}, {%4, %5, %6, %7}, {%8, %9}, {%0, %1, %2, %3};"   \
        : "+f"((d)[0]), "+f"((d)[1]), "+f"((d)[2]), "+f"((d)[3])            \
        : "r"((a)[0]), "r"((a)[1]), "r"((a)[2]), "r"((a)[3]),               \
          "r"((b)[0]), "r"((b)[1]))

#define CPA16(dst, src, sz)                                                 \
    asm volatile("cp.async.cg.shared.global [%0], [%1], 16, %2;"            \
                 :: "r"(dst), "l"(src), "r"(sz))
#define CPA_COMMIT() asm volatile("cp.async.commit_group;" ::: "memory")
#define CPA_WAIT1()  asm volatile("cp.async.wait_group 1;" ::: "memory")
#define CPA_WAIT0()  asm volatile("cp.async.wait_group 0;" ::: "memory")

#define SWZ(o)   ((o) ^ (((o) >> 3) & 0x70))   // 128B rows
#define SWZ64(o) ((o) ^ (((o) >> 3) & 0x30))   // 64B rows

__device__ __forceinline__ uint32_t packbf(float x, float y) {
    __nv_bfloat162 t;
    t.x = __float2bfloat16(x);
    t.y = __float2bfloat16(y);
    return *(uint32_t*)&t;
}
__device__ __forceinline__ float bflo(float x) {
    return x - __bfloat162float(__float2bfloat16(x));
}

// ===========================================================================
// fp32 -> bf16 hi/lo split (one pass, vectorized x8)
// ===========================================================================
__global__ void split_k(const float* __restrict__ in,
                        __nv_bfloat16* __restrict__ hi,
                        __nv_bfloat16* __restrict__ lo, int n8) {
    int i = blockIdx.x * blockDim.x + threadIdx.x;
    if (i >= n8) return;
    const float4* p = (const float4*)in + (size_t)i * 2;
    float4 v0 = p[0], v1 = p[1];
    float v[8] = {v0.x, v0.y, v0.z, v0.w, v1.x, v1.y, v1.z, v1.w};
    __nv_bfloat16 h[8], l[8];
#pragma unroll
    for (int j = 0; j < 8; j++) {
        h[j] = __float2bfloat16(v[j]);
        l[j] = __float2bfloat16(v[j] - __bfloat162float(h[j]));
    }
    ((uint4*)hi)[i] = *(uint4*)h;
    ((uint4*)lo)[i] = *(uint4*)l;
}

// ===========================================================================
// mma.sync GEMM, bf16x3 emulated-fp32, 3-stage cp.async pipeline, occ 2:
//   C[m,n] = sum_k A[m,k]*W[n,k] + bias[n]
// CTA 128x128, K-chunk 32 (64B rows, SW64), 256 threads (8 warps 32m x 64n).
// smem: bias 512B @0; stage s @ 1024 + s*32768, arrays {AH,AL,BH,BL} x 8KB.
// ===========================================================================
#define G_ST(s)  (1024 + (s) * 32768)
#define G_AH 0
#define G_AL 8192
#define G_BH 16384
#define G_BL 24576
#define GEMM_SMEM (1024 + 3 * 32768)
#define NCHUNK 32

__global__ __launch_bounds__(256, 2)
void gemm_mma(const __nv_bfloat16* __restrict__ Ah,
              const __nv_bfloat16* __restrict__ Al,
              const __nv_bfloat16* __restrict__ Bh,
              const __nv_bfloat16* __restrict__ Bl,
              const float* __restrict__ bias,
              float* __restrict__ C,
              __nv_bfloat16* __restrict__ Ch,
              __nv_bfloat16* __restrict__ Cl,
              int splitout) {
    extern __shared__ char sm[];
    const uint32_t sbase = smem_u32(sm);
    float* sbias = (float*)sm;

    const int tid = threadIdx.x;
    const int wid = tid >> 5, lane = tid & 31;
    const int n0 = blockIdx.x * 128, m0 = blockIdx.y * 128;

    if (tid < 128) sbias[tid] = bias[n0 + tid];

    const int wm = (wid & 3) * 32;
    const int wn = (wid >> 2) * 64;

    float acc[2][8][4];
#pragma unroll
    for (int mt = 0; mt < 2; mt++)
#pragma unroll
        for (int nt = 0; nt < 8; nt++)
#pragma unroll
            for (int e = 0; e < 4; e++) acc[mt][nt][e] = 0.f;

    const int cr = tid >> 1;            // 0..127: row
    const int hcE = (tid & 1) * 16;     // element offset (bf16)
    const int localr = lane & 7, sel = lane >> 3;

    const __nv_bfloat16* rowA_h = Ah + (size_t)(m0 + cr) * DD + hcE;
    const __nv_bfloat16* rowA_l = Al + (size_t)(m0 + cr) * DD + hcE;
    const __nv_bfloat16* rowB_h = Bh + (size_t)(n0 + cr) * DD + hcE;
    const __nv_bfloat16* rowB_l = Bl + (size_t)(n0 + cr) * DD + hcE;

#define G_STAGE(c, s)                                                       \
    do {                                                                    \
        const uint32_t stb = sbase + G_ST(s);                               \
        _Pragma("unroll")                                                   \
        for (int j = 0; j < 2; j++) {                                       \
            uint32_t off = SWZ64((uint32_t)(cr * 64 + hcE * 2 + 16 * j));   \
            CPA16(stb + G_AH + off, rowA_h + (size_t)(c) * 32 + 8 * j, 16); \
            CPA16(stb + G_AL + off, rowA_l + (size_t)(c) * 32 + 8 * j, 16); \
            CPA16(stb + G_BH + off, rowB_h + (size_t)(c) * 32 + 8 * j, 16); \
            CPA16(stb + G_BL + off, rowB_l + (size_t)(c) * 32 + 8 * j, 16); \
        }                                                                   \
        CPA_COMMIT();                                                       \
    } while (0)

    G_STAGE(0, 0);
    G_STAGE(1, 1);

    for (int c = 0; c < NCHUNK; c++) {
        const int s = c % 3;
        if (c + 1 < NCHUNK) CPA_WAIT1(); else CPA_WAIT0();
        __syncthreads();
        if (c + 2 < NCHUNK) G_STAGE(c + 2, (c + 2) % 3);

        const uint32_t stb = sbase + G_ST(s);
#pragma unroll
        for (int kk = 0; kk < 32; kk += 16) {
            uint32_t ah[2][4], al[2][4];
#pragma unroll
            for (int mt = 0; mt < 2; mt++) {
                const int row = wm + mt * 16 + localr + (sel & 1) * 8;
                const int kb = kk + (sel >> 1) * 8;
                const uint32_t off = SWZ64((uint32_t)(row * 64 + kb * 2));
                LDSM_X4(ah[mt][0], ah[mt][1], ah[mt][2], ah[mt][3],
                        stb + G_AH + off);
                LDSM_X4(al[mt][0], al[mt][1], al[mt][2], al[mt][3],
                        stb + G_AL + off);
            }
            uint32_t bh[8][2], bl[8][2];
#pragma unroll
            for (int np = 0; np < 4; np++) {
                const int row = wn + np * 16 + (sel >> 1) * 8 + localr;
                const int kb = kk + (sel & 1) * 8;
                const uint32_t off = SWZ64((uint32_t)(row * 64 + kb * 2));
                uint32_t t0, t1, t2, t3;
                LDSM_X4(t0, t1, t2, t3, stb + G_BH + off);
                bh[2 * np][0] = t0; bh[2 * np][1] = t1;
                bh[2 * np + 1][0] = t2; bh[2 * np + 1][1] = t3;
                LDSM_X4(t0, t1, t2, t3, stb + G_BL + off);
                bl[2 * np][0] = t0; bl[2 * np][1] = t1;
                bl[2 * np + 1][0] = t2; bl[2 * np + 1][1] = t3;
            }
#pragma unroll
            for (int mt = 0; mt < 2; mt++)
#pragma unroll
                for (int nt = 0; nt < 8; nt++) {
                    MMA16816(acc[mt][nt], ah[mt], bh[nt]);
                    MMA16816(acc[mt][nt], ah[mt], bl[nt]);
                    MMA16816(acc[mt][nt], al[mt], bh[nt]);
                }
        }
    }

    const int er = lane >> 2;
    const int ec = (lane & 3) * 2;
#pragma unroll
    for (int mt = 0; mt < 2; mt++) {
#pragma unroll
        for (int nt = 0; nt < 8; nt++) {
            const int ct = wn + nt * 8 + ec;
            const int row0 = m0 + wm + mt * 16 + er;
            float x0 = acc[mt][nt][0] + sbias[ct];
            float x1 = acc[mt][nt][1] + sbias[ct + 1];
            float x2 = acc[mt][nt][2] + sbias[ct];
            float x3 = acc[mt][nt][3] + sbias[ct + 1];
            const size_t i0 = (size_t)row0 * DD + n0 + ct;
            const size_t i1 = (size_t)(row0 + 8) * DD + n0 + ct;
            if (splitout) {
                *(uint32_t*)&Ch[i0] = packbf(x0, x1);
                *(uint32_t*)&Cl[i0] = packbf(bflo(x0), bflo(x1));
                *(uint32_t*)&Ch[i1] = packbf(x2, x3);
                *(uint32_t*)&Cl[i1] = packbf(bflo(x2), bflo(x3));
            } else {
                float2 v0 = {x0, x1}, v1 = {x2, x3};
                *(float2*)&C[i0] = v0;
                *(float2*)&C[i1] = v1;
            }
        }
    }
}

// ===========================================================================
// mma.sync sliding-window flash attention, bf16x3, 2-stage cp.async,
// online softmax in registers, interior-tile mask fast path.
// CTA = 128 queries x 1 head, 8 warps (16 q-rows each).
// ===========================================================================
#define A_QH 0
#define A_QL 16384
#define A_ST(s) (32768 + (s) * 32768)
#define A_KH 0
#define A_KL 8192
#define A_VH 16384
#define A_VL 24576
#define ATT_SMEM (32768 + 2 * 32768)

__global__ __launch_bounds__(256, 2)
void attn_mma(const __nv_bfloat16* __restrict__ Qh,
              const __nv_bfloat16* __restrict__ Ql,
              const __nv_bfloat16* __restrict__ Kh,
              const __nv_bfloat16* __restrict__ Kl,
              const __nv_bfloat16* __restrict__ Vh,
              const __nv_bfloat16* __restrict__ Vl,
              __nv_bfloat16* __restrict__ Oh,
              __nv_bfloat16* __restrict__ Ol) {
    extern __shared__ char sm[];
    const uint32_t sbase = smem_u32(sm);

    const int tid = threadIdx.x;
    const int wid = tid >> 5, lane = tid & 31;
    const int qs = blockIdx.x * 128;
    const int hoff = blockIdx.y * HDIM;
    const int localr = lane & 7, sel = lane >> 3;

    // ---- stage Q tile (128 x 64 bf16 hi/lo), swizzled 128B rows ----
    {
        const int r = tid >> 1;
        const int half = (tid & 1) * 32;
        const size_t g = (size_t)(qs + r) * DD + hoff + half;
#pragma unroll
        for (int j = 0; j < 4; j++) {
            uint32_t off = SWZ((uint32_t)(r * 128 + (half + 8 * j) * 2));
            *(uint4*)(sm + A_QH + off) = *(const uint4*)&Qh[g + 8 * j];
            *(uint4*)(sm + A_QL + off) = *(const uint4*)&Ql[g + 8 * j];
        }
    }

    // valid tile range (SS, qs, tiles all 64-aligned => tiles never partial)
    const int t0v = max(0, (512 - qs + 63) / 64);
    const int t1v = min(18, (SS + 512 - qs) / 64);

    const int svr = tid >> 2;
    const int svc = (tid & 3) * 16;

#define A_STAGE(t, s)                                                       \
    do {                                                                    \
        const int kabs_ = qs - 512 + 64 * (t) + svr;                        \
        const size_t g_ = (size_t)kabs_ * DD + hoff + svc;                  \
        const uint32_t stb_ = sbase + A_ST(s);                              \
        _Pragma("unroll")                                                   \
        for (int j = 0; j < 2; j++) {                                       \
            uint32_t off = SWZ((uint32_t)(svr * 128 + (svc + 8 * j) * 2));  \
            CPA16(stb_ + A_KH + off, &Kh[g_ + 8 * j], 16u);                 \
            CPA16(stb_ + A_KL + off, &Kl[g_ + 8 * j], 16u);                 \
            CPA16(stb_ + A_VH + off, &Vh[g_ + 8 * j], 16u);                 \
            CPA16(stb_ + A_VL + off, &Vl[g_ + 8 * j], 16u);                 \
        }                                                                   \
        CPA_COMMIT();                                                       \
    } while (0)

    const int q0 = qs + 16 * wid + (lane >> 2);
    const int q1 = q0 + 8;

    float m0 = -1e30f, m1 = -1e30f, l0 = 0.f, l1 = 0.f;
    float oacc[8][4];
#pragma unroll
    for (int nt = 0; nt < 8; nt++)
#pragma unroll
        for (int e = 0; e < 4; e++) oacc[nt][e] = 0.f;

    A_STAGE(t0v, 0);

    for (int t = t0v; t < t1v; t++) {
        const int s = (t - t0v) & 1;
        const int kt = qs - 512 + 64 * t;
        CPA_WAIT0();
        __syncthreads();
        if (t + 1 < t1v) A_STAGE(t + 1, s ^ 1);

        const uint32_t stb = sbase + A_ST(s);

        // ---- QK^T: S (16q x 64k per warp) ----
        float sacc[8][4];
#pragma unroll
        for (int nt = 0; nt < 8; nt++)
#pragma unroll
            for (int e = 0; e < 4; e++) sacc[nt][e] = 0.f;

#pragma unroll
        for (int kk = 0; kk < 64; kk += 16) {
            uint32_t qhf[4], qlf[4];
            {
                const int row = 16 * wid + localr + (sel & 1) * 8;
                const int kb = kk + (sel >> 1) * 8;
                const uint32_t off = SWZ((uint32_t)(row * 128 + kb * 2));
                LDSM_X4(qhf[0], qhf[1], qhf[2], qhf[3], sbase + A_QH + off);
                LDSM_X4(qlf[0], qlf[1], qlf[2], qlf[3], sbase + A_QL + off);
            }
            uint32_t khf[8][2], klf[8][2];
#pragma unroll
            for (int np = 0; np < 4; np++) {
                const int row = np * 16 + (sel >> 1) * 8 + localr;
                const int kb = kk + (sel & 1) * 8;
                const uint32_t off = SWZ((uint32_t)(row * 128 + kb * 2));
                uint32_t t0r, t1r, t2r, t3r;
                LDSM_X4(t0r, t1r, t2r, t3r, stb + A_KH + off);
                khf[2 * np][0] = t0r; khf[2 * np][1] = t1r;
                khf[2 * np + 1][0] = t2r; khf[2 * np + 1][1] = t3r;
                LDSM_X4(t0r, t1r, t2r, t3r, stb + A_KL + off);
                klf[2 * np][0] = t0r; klf[2 * np][1] = t1r;
                klf[2 * np + 1][0] = t2r; klf[2 * np + 1][1] = t3r;
            }
#pragma unroll
            for (int nt = 0; nt < 8; nt++) {
                MMA16816(sacc[nt], qhf, khf[nt]);
                MMA16816(sacc[nt], qhf, klf[nt]);
                MMA16816(sacc[nt], qlf, khf[nt]);
            }
        }

        // ---- scale (+ window mask on edge tiles only) + row max ----
        float mx0 = -1e30f, mx1 = -1e30f;
        if (t < 2 || t > 15) {
            const int cb = kt + 2 * (lane & 3);
#pragma unroll
            for (int nt = 0; nt < 8; nt++) {
#pragma unroll
                for (int e = 0; e < 2; e++) {
                    const int kabs = cb + 8 * nt + e;
                    float s0 = ((kabs >= q0 - 512) & (kabs < q0 + 512))
                                   ? sacc[nt][e] * 0.125f : -1e30f;
                    float s1 = ((kabs >= q1 - 512) & (kabs < q1 + 512))
                                   ? sacc[nt][e + 2] * 0.125f : -1e30f;
                    sacc[nt][e] = s0; sacc[nt][e + 2] = s1;
                    mx0 = fmaxf(mx0, s0); mx1 = fmaxf(mx1, s1);
                }
            }
        } else {
#pragma unroll
            for (int nt = 0; nt < 8; nt++) {
#pragma unroll
                for (int e = 0; e < 2; e++) {
                    float s0 = sacc[nt][e] * 0.125f;
                    float s1 = sacc[nt][e + 2] * 0.125f;
                    sacc[nt][e] = s0; sacc[nt][e + 2] = s1;
                    mx0 = fmaxf(mx0, s0); mx1 = fmaxf(mx1, s1);
                }
            }
        }
        mx0 = fmaxf(mx0, __shfl_xor_sync(0xffffffffu, mx0, 1));
        mx0 = fmaxf(mx0, __shfl_xor_sync(0xffffffffu, mx0, 2));
        mx1 = fmaxf(mx1, __shfl_xor_sync(0xffffffffu, mx1, 1));
        mx1 = fmaxf(mx1, __shfl_xor_sync(0xffffffffu, mx1, 2));
        const float mn0 = fmaxf(m0, mx0), mn1 = fmaxf(m1, mx1);
        const float a0 = __expf(m0 - mn0), a1 = __expf(m1 - mn1);
        m0 = mn0; m1 = mn1;
        float rs0 = 0.f, rs1 = 0.f;
#pragma unroll
        for (int nt = 0; nt < 8; nt++) {
#pragma unroll
            for (int e = 0; e < 2; e++) {
                float p0 = (sacc[nt][e] > -5e29f) ? __expf(sacc[nt][e] - mn0) : 0.f;
                float p1 = (sacc[nt][e + 2] > -5e29f) ? __expf(sacc[nt][e + 2] - mn1) : 0.f;
                rs0 += p0; rs1 += p1;
                sacc[nt][e] = p0; sacc[nt][e + 2] = p1;
            }
        }
        l0 = l0 * a0 + rs0;
        l1 = l1 * a1 + rs1;
#pragma unroll
        for (int nt = 0; nt < 8; nt++) {
            oacc[nt][0] *= a0; oacc[nt][1] *= a0;
            oacc[nt][2] *= a1; oacc[nt][3] *= a1;
        }

        // ---- PV: O += P * V ----
#pragma unroll
        for (int kc = 0; kc < 4; kc++) {
            uint32_t pah[4], pal[4];
            pah[0] = packbf(sacc[2 * kc][0], sacc[2 * kc][1]);
            pah[1] = packbf(sacc[2 * kc][2], sacc[2 * kc][3]);
            pah[2] = packbf(sacc[2 * kc + 1][0], sacc[2 * kc + 1][1]);
            pah[3] = packbf(sacc[2 * kc + 1][2], sacc[2 * kc + 1][3]);
            pal[0] = packbf(bflo(sacc[2 * kc][0]), bflo(sacc[2 * kc][1]));
            pal[1] = packbf(bflo(sacc[2 * kc][2]), bflo(sacc[2 * kc][3]));
            pal[2] = packbf(bflo(sacc[2 * kc + 1][0]), bflo(sacc[2 * kc + 1][1]));
            pal[3] = packbf(bflo(sacc[2 * kc + 1][2]), bflo(sacc[2 * kc + 1][3]));

            uint32_t vhf[8][2], vlf[8][2];
#pragma unroll
            for (int ntp = 0; ntp < 4; ntp++) {
                const int key = 16 * kc + (sel & 1) * 8 + localr;
                const int dim = (2 * ntp + (sel >> 1)) * 8;
                const uint32_t off = SWZ((uint32_t)(key * 128 + dim * 2));
                uint32_t t0r, t1r, t2r, t3r;
                LDSM_X4_T(t0r, t1r, t2r, t3r, stb + A_VH + off);
                vhf[2 * ntp][0] = t0r; vhf[2 * ntp][1] = t1r;
                vhf[2 * ntp + 1][0] = t2r; vhf[2 * ntp + 1][1] = t3r;
                LDSM_X4_T(t0r, t1r, t2r, t3r, stb + A_VL + off);
                vlf[2 * ntp][0] = t0r; vlf[2 * ntp][1] = t1r;
                vlf[2 * ntp + 1][0] = t2r; vlf[2 * ntp + 1][1] = t3r;
            }
#pragma unroll
            for (int nt = 0; nt < 8; nt++) {
                MMA16816(oacc[nt], pah, vhf[nt]);
                MMA16816(oacc[nt], pah, vlf[nt]);
                MMA16816(oacc[nt], pal, vhf[nt]);
            }
        }
    }

    // ---- epilogue: normalize, blend weight, write bf16 hi/lo ----
    l0 += __shfl_xor_sync(0xffffffffu, l0, 1);
    l0 += __shfl_xor_sync(0xffffffffu, l0, 2);
    l1 += __shfl_xor_sync(0xffffffffu, l1, 1);
    l1 += __shfl_xor_sync(0xffffffffu, l1, 2);
    float w0 = 1.f, w1 = 1.f;
    if (q0 >= SS - 128) w0 = 1.f + (float)(q0 - (SS - 128)) * (1.f / 127.f);
    if (q1 >= SS - 128) w1 = 1.f + (float)(q1 - (SS - 128)) * (1.f / 127.f);
    const float sc0 = w0 / l0, sc1 = w1 / l1;
    const int ec = 2 * (lane & 3);
#pragma unroll
    for (int nt = 0; nt < 8; nt++) {
        const size_t i0 = (size_t)q0 * DD + hoff + 8 * nt + ec;
        const size_t i1 = (size_t)q1 * DD + hoff + 8 * nt + ec;
        float x0 = oacc[nt][0] * sc0, x1 = oacc[nt][1] * sc0;
        float x2 = oacc[nt][2] * sc1, x3 = oacc[nt][3] * sc1;
        *(uint32_t*)&Oh[i0] = packbf(x0, x1);
        *(uint32_t*)&Ol[i0] = packbf(bflo(x0), bflo(x1));
        *(uint32_t*)&Oh[i1] = packbf(x2, x3);
        *(uint32_t*)&Ol[i1] = packbf(bflo(x2), bflo(x3));
    }
}

// ===========================================================================
extern "C" void kernel_launch(void* const* d_in, const int* in_sizes, int n_in,
                              void* d_out, int out_size) {
    const float* x = nullptr;
    const float* Wm[4] = {nullptr, nullptr, nullptr, nullptr};
    const float* bm[4] = {nullptr, nullptr, nullptr, nullptr};
    int nw = 0, nb = 0;
    for (int i = 0; i < n_in; i++) {
        const float* p = (const float*)d_in[i];
        if (in_sizes[i] == SS * DD) x = p;
        else if (in_sizes[i] == DD * DD) { if (nw < 4) Wm[nw++] = p; }
        else if (in_sizes[i] == DD) { if (nb < 4) bm[nb++] = p; }
    }
    float* out = (float*)d_out;

    __nv_bfloat16 *xh, *xl, *Wh, *Wl, *Qh, *Ql, *Kh, *Kl, *Vh, *Vl, *Oh, *Ol;
    cudaGetSymbolAddress((void**)&xh, g_xh);
    cudaGetSymbolAddress((void**)&xl, g_xl);
    cudaGetSymbolAddress((void**)&Wh, g_Wh);
    cudaGetSymbolAddress((void**)&Wl, g_Wl);
    cudaGetSymbolAddress((void**)&Qh, g_Qh);
    cudaGetSymbolAddress((void**)&Ql, g_Ql);
    cudaGetSymbolAddress((void**)&Kh, g_Kh);
    cudaGetSymbolAddress((void**)&Kl, g_Kl);
    cudaGetSymbolAddress((void**)&Vh, g_Vh);
    cudaGetSymbolAddress((void**)&Vl, g_Vl);
    cudaGetSymbolAddress((void**)&Oh, g_Oh);
    cudaGetSymbolAddress((void**)&Ol, g_Ol);

    // ---- split inputs to bf16 hi/lo ----
    split_k<<<(SS * DD / 8 + 255) / 256, 256>>>(x, xh, xl, SS * DD / 8);
    for (int w = 0; w < 4; w++)
        split_k<<<(DD * DD / 8 + 255) / 256, 256>>>(
            Wm[w], Wh + (size_t)w * DD * DD, Wl + (size_t)w * DD * DD,
            DD * DD / 8);

    cudaFuncSetAttribute(gemm_mma, cudaFuncAttributeMaxDynamicSharedMemorySize,
                         GEMM_SMEM);
    cudaFuncSetAttribute(attn_mma, cudaFuncAttributeMaxDynamicSharedMemorySize,
                         ATT_SMEM);

    dim3 ggrid(DD / 128, SS / 128);
    gemm_mma<<<ggrid, 256, GEMM_SMEM>>>(xh, xl, Wh, Wl, bm[0],
                                        nullptr, Qh, Ql, 1);
    gemm_mma<<<ggrid, 256, GEMM_SMEM>>>(xh, xl, Wh + (size_t)1 * DD * DD,
                                        Wl + (size_t)1 * DD * DD, bm[1],
                                        nullptr, Kh, Kl, 1);
    gemm_mma<<<ggrid, 256, GEMM_SMEM>>>(xh, xl, Wh + (size_t)2 * DD * DD,
                                        Wl + (size_t)2 * DD * DD, bm[2],
                                        nullptr, Vh, Vl, 1);

    attn_mma<<<dim3(SS / 128, HH), 256, ATT_SMEM>>>(Qh, Ql, Kh, Kl, Vh, Vl,
                                                    Oh, Ol);

    gemm_mma<<<ggrid, 256, GEMM_SMEM>>>(Oh, Ol, Wh + (size_t)3 * DD * DD,
                                        Wl + (size_t)3 * DD * DD, bm[3],
                                        out, nullptr, nullptr, 0);
}

// round 10
// speedup vs baseline: 2.6691x; 1.0516x over previous
#include <cuda_runtime.h>
#include <cuda_bf16.h>
#include <stdint.h>
#include <math.h>

#define SS 8192
#define DD 1024
#define HH 16
#define HDIM 64

// ---- scratch: bf16 hi/lo pairs (static device arrays) ----
__device__ __nv_bfloat16 g_xh[SS * DD], g_xl[SS * DD];
__device__ __nv_bfloat16 g_Wh[4][DD * DD], g_Wl[4][DD * DD];
__device__ __nv_bfloat16 g_Qh[SS * DD], g_Ql[SS * DD];
__device__ __nv_bfloat16 g_Kh[SS * DD], g_Kl[SS * DD];
__device__ __nv_bfloat16 g_Vh[SS * DD], g_Vl[SS * DD];
__device__ __nv_bfloat16 g_Oh[SS * DD], g_Ol[SS * DD];

// ===========================================================================
// PTX helpers (baseline ISA: ldmatrix + mma.sync + cp.async, sm_80+)
// ===========================================================================
__device__ __forceinline__ uint32_t smem_u32(const void* p) {
    uint32_t a;
    asm("{ .reg .u64 t; cvta.to.shared.u64 t, %1; cvt.u32.u64 %0, t; }"
        : "=r"(a) : "l"(p));
    return a;
}

#define LDSM_X4(r0, r1, r2, r3, addr)                                       \
    asm volatile(                                                           \
        "ldmatrix.sync.aligned.m8n8.x4.shared.b16 {%0, %1, %2, %3}, [%4];"  \
        : "=r"(r0), "=r"(r1), "=r"(r2), "=r"(r3) : "r"(addr))

#define LDSM_X4_T(r0, r1, r2, r3, addr)                                     \
    asm volatile(                                                           \
        "ldmatrix.sync.aligned.m8n8.x4.trans.shared.b16 {%0, %1, %2, %3}, [%4];" \
        : "=r"(r0), "=r"(r1), "=r"(r2), "=r"(r3) : "r"(addr))

#define MMA16816(d, a, b)                                                   \
    asm volatile(                                                           \
        "mma.sync.aligned.m16n8k16.row.col.f32.bf16.bf16.f32 "              \
        "{%0, %1, %2, %3}, {%4, %5, %6, %7}, {%8, %9}, {%0, %1, %2, %3};"   \
        : "+f"((d)[0]), "+f"((d)[1]), "+f"((d)[2]), "+f"((d)[3])            \
        : "r"((a)[0]), "r"((a)[1]), "r"((a)[2]), "r"((a)[3]),               \
          "r"((b)[0]), "r"((b)[1]))

#define CPA16(dst, src, sz)                                                 \
    asm volatile("cp.async.cg.shared.global [%0], [%1], 16, %2;"            \
                 :: "r"(dst), "l"(src), "r"(sz))
#define CPA_COMMIT() asm volatile("cp.async.commit_group;" ::: "memory")
#define CPA_WAIT1()  asm volatile("cp.async.wait_group 1;" ::: "memory")
#define CPA_WAIT0()  asm volatile("cp.async.wait_group 0;" ::: "memory")

#define SWZ(o)   ((o) ^ (((o) >> 3) & 0x70))   // 128B rows
#define SWZ64(o) ((o) ^ (((o) >> 3) & 0x30))   // 64B rows

// Single-instruction bf16x2 pack: {lo=x, hi=y}, round-to-nearest.
__device__ __forceinline__ uint32_t packbf(float x, float y) {
    uint32_t r;
    asm("cvt.rn.bf16x2.f32 %0, %1, %2;" : "=r"(r) : "f"(y), "f"(x));
    return r;
}
// hi/lo split of a float pair: h = bf16x2(x,y); l = bf16x2 of residues.
__device__ __forceinline__ void split2(float x, float y,
                                       uint32_t& h, uint32_t& l) {
    h = packbf(x, y);
    float hx = __uint_as_float(h << 16);
    float hy = __uint_as_float(h & 0xffff0000u);
    l = packbf(x - hx, y - hy);
}

// ===========================================================================
// Fused fp32 -> bf16 hi/lo split for x + the 4 weight matrices (one launch).
// Index space in units of 8 floats: [0, NX8) -> x, then 4 x NW8 -> W[w].
// ===========================================================================
#define NX8 (SS * DD / 8)
#define NW8 (DD * DD / 8)

__global__ void split_all(const float* __restrict__ x,
                          const float* __restrict__ w0,
                          const float* __restrict__ w1,
                          const float* __restrict__ w2,
                          const float* __restrict__ w3,
                          __nv_bfloat16* __restrict__ xh,
                          __nv_bfloat16* __restrict__ xl,
                          __nv_bfloat16* __restrict__ Wh,
                          __nv_bfloat16* __restrict__ Wl) {
    int idx = blockIdx.x * blockDim.x + threadIdx.x;
    if (idx >= NX8 + 4 * NW8) return;
    const float* src;
    __nv_bfloat16 *dh, *dl;
    size_t off;
    if (idx < NX8) {
        src = x; dh = xh; dl = xl; off = idx;
    } else {
        int r = idx - NX8;
        int w = r >> 17;           // / NW8 (2^17)
        int o = r & (NW8 - 1);
        const float* ws[4] = {w0, w1, w2, w3};
        src = ws[w];
        dh = Wh + (size_t)w * DD * DD;
        dl = Wl + (size_t)w * DD * DD;
        off = o;
    }
    const float4* p = (const float4*)src + off * 2;
    float4 v0 = p[0], v1 = p[1];
    uint32_t h[4], l[4];
    split2(v0.x, v0.y, h[0], l[0]);
    split2(v0.z, v0.w, h[1], l[1]);
    split2(v1.x, v1.y, h[2], l[2]);
    split2(v1.z, v1.w, h[3], l[3]);
    ((uint4*)dh)[off] = *(uint4*)h;
    ((uint4*)dl)[off] = *(uint4*)l;
}

// ===========================================================================
// Shared GEMM core: mma.sync, bf16x3 emulated-fp32, 3-stage cp.async, occ 2.
//   C[m,n] = sum_k A[m,k]*W[n,k] + bias[n]
// CTA 128x128, K-chunk 32 (64B rows, SW64), 256 threads (8 warps 32m x 64n).
// ===========================================================================
#define G_ST(s)  (1024 + (s) * 32768)
#define G_AH 0
#define G_AL 8192
#define G_BH 16384
#define G_BL 24576
#define GEMM_SMEM (1024 + 3 * 32768)
#define NCHUNK 32

__device__ __forceinline__ void gemm_core(
    const __nv_bfloat16* __restrict__ Ah, const __nv_bfloat16* __restrict__ Al,
    const __nv_bfloat16* __restrict__ Bh, const __nv_bfloat16* __restrict__ Bl,
    const float* __restrict__ bias, float* __restrict__ C,
    __nv_bfloat16* __restrict__ Ch, __nv_bfloat16* __restrict__ Cl,
    bool splitout, char* sm) {
    const uint32_t sbase = smem_u32(sm);
    float* sbias = (float*)sm;

    const int tid = threadIdx.x;
    const int wid = tid >> 5, lane = tid & 31;
    const int n0 = blockIdx.x * 128, m0 = blockIdx.y * 128;

    if (tid < 128) sbias[tid] = bias[n0 + tid];

    const int wm = (wid & 3) * 32;
    const int wn = (wid >> 2) * 64;

    float acc[2][8][4];
#pragma unroll
    for (int mt = 0; mt < 2; mt++)
#pragma unroll
        for (int nt = 0; nt < 8; nt++)
#pragma unroll
            for (int e = 0; e < 4; e++) acc[mt][nt][e] = 0.f;

    const int cr = tid >> 1;
    const int hcE = (tid & 1) * 16;
    const int localr = lane & 7, sel = lane >> 3;

    const __nv_bfloat16* rowA_h = Ah + (size_t)(m0 + cr) * DD + hcE;
    const __nv_bfloat16* rowA_l = Al + (size_t)(m0 + cr) * DD + hcE;
    const __nv_bfloat16* rowB_h = Bh + (size_t)(n0 + cr) * DD + hcE;
    const __nv_bfloat16* rowB_l = Bl + (size_t)(n0 + cr) * DD + hcE;

#define G_STAGE(c, s)                                                       \
    do {                                                                    \
        const uint32_t stb = sbase + G_ST(s);                               \
        _Pragma("unroll")                                                   \
        for (int j = 0; j < 2; j++) {                                       \
            uint32_t off = SWZ64((uint32_t)(cr * 64 + hcE * 2 + 16 * j));   \
            CPA16(stb + G_AH + off, rowA_h + (size_t)(c) * 32 + 8 * j, 16); \
            CPA16(stb + G_AL + off, rowA_l + (size_t)(c) * 32 + 8 * j, 16); \
            CPA16(stb + G_BH + off, rowB_h + (size_t)(c) * 32 + 8 * j, 16); \
            CPA16(stb + G_BL + off, rowB_l + (size_t)(c) * 32 + 8 * j, 16); \
        }                                                                   \
        CPA_COMMIT();                                                       \
    } while (0)

    G_STAGE(0, 0);
    G_STAGE(1, 1);

    for (int c = 0; c < NCHUNK; c++) {
        const int s = c % 3;
        if (c + 1 < NCHUNK) CPA_WAIT1(); else CPA_WAIT0();
        __syncthreads();
        if (c + 2 < NCHUNK) G_STAGE(c + 2, (c + 2) % 3);

        const uint32_t stb = sbase + G_ST(s);
#pragma unroll
        for (int kk = 0; kk < 32; kk += 16) {
            uint32_t ah[2][4], al[2][4];
#pragma unroll
            for (int mt = 0; mt < 2; mt++) {
                const int row = wm + mt * 16 + localr + (sel & 1) * 8;
                const int kb = kk + (sel >> 1) * 8;
                const uint32_t off = SWZ64((uint32_t)(row * 64 + kb * 2));
                LDSM_X4(ah[mt][0], ah[mt][1], ah[mt][2], ah[mt][3],
                        stb + G_AH + off);
                LDSM_X4(al[mt][0], al[mt][1], al[mt][2], al[mt][3],
                        stb + G_AL + off);
            }
            uint32_t bh[8][2], bl[8][2];
#pragma unroll
            for (int np = 0; np < 4; np++) {
                const int row = wn + np * 16 + (sel >> 1) * 8 + localr;
                const int kb = kk + (sel & 1) * 8;
                const uint32_t off = SWZ64((uint32_t)(row * 64 + kb * 2));
                uint32_t t0, t1, t2, t3;
                LDSM_X4(t0, t1, t2, t3, stb + G_BH + off);
                bh[2 * np][0] = t0; bh[2 * np][1] = t1;
                bh[2 * np + 1][0] = t2; bh[2 * np + 1][1] = t3;
                LDSM_X4(t0, t1, t2, t3, stb + G_BL + off);
                bl[2 * np][0] = t0; bl[2 * np][1] = t1;
                bl[2 * np + 1][0] = t2; bl[2 * np + 1][1] = t3;
            }
#pragma unroll
            for (int mt = 0; mt < 2; mt++)
#pragma unroll
                for (int nt = 0; nt < 8; nt++) {
                    MMA16816(acc[mt][nt], ah[mt], bh[nt]);
                    MMA16816(acc[mt][nt], ah[mt], bl[nt]);
                    MMA16816(acc[mt][nt], al[mt], bh[nt]);
                }
        }
    }

    const int er = lane >> 2;
    const int ec = (lane & 3) * 2;
#pragma unroll
    for (int mt = 0; mt < 2; mt++) {
#pragma unroll
        for (int nt = 0; nt < 8; nt++) {
            const int ct = wn + nt * 8 + ec;
            const int row0 = m0 + wm + mt * 16 + er;
            float x0 = acc[mt][nt][0] + sbias[ct];
            float x1 = acc[mt][nt][1] + sbias[ct + 1];
            float x2 = acc[mt][nt][2] + sbias[ct];
            float x3 = acc[mt][nt][3] + sbias[ct + 1];
            const size_t i0 = (size_t)row0 * DD + n0 + ct;
            const size_t i1 = (size_t)(row0 + 8) * DD + n0 + ct;
            if (splitout) {
                uint32_t h0, l0u, h1, l1u;
                split2(x0, x1, h0, l0u);
                split2(x2, x3, h1, l1u);
                *(uint32_t*)&Ch[i0] = h0;
                *(uint32_t*)&Cl[i0] = l0u;
                *(uint32_t*)&Ch[i1] = h1;
                *(uint32_t*)&Cl[i1] = l1u;
            } else {
                float2 v0 = {x0, x1}, v1 = {x2, x3};
                *(float2*)&C[i0] = v0;
                *(float2*)&C[i1] = v1;
            }
        }
    }
#undef G_STAGE
}

// Fused Q/K/V projections: blockIdx.z selects the weight/bias/output triple.
struct QKVArgs {
    const __nv_bfloat16* Bh[3];
    const __nv_bfloat16* Bl[3];
    const float* bias[3];
    __nv_bfloat16* Ch[3];
    __nv_bfloat16* Cl[3];
};

__global__ __launch_bounds__(256, 2)
void gemm_qkv(const __nv_bfloat16* __restrict__ Ah,
              const __nv_bfloat16* __restrict__ Al, QKVArgs a) {
    extern __shared__ char sm[];
    const int w = blockIdx.z;
    gemm_core(Ah, Al, a.Bh[w], a.Bl[w], a.bias[w], nullptr,
              a.Ch[w], a.Cl[w], true, sm);
}

__global__ __launch_bounds__(256, 2)
void gemm_out(const __nv_bfloat16* __restrict__ Ah,
              const __nv_bfloat16* __restrict__ Al,
              const __nv_bfloat16* __restrict__ Bh,
              const __nv_bfloat16* __restrict__ Bl,
              const float* __restrict__ bias, float* __restrict__ C) {
    extern __shared__ char sm[];
    gemm_core(Ah, Al, Bh, Bl, bias, C, nullptr, nullptr, false, sm);
}

// ===========================================================================
// mma.sync sliding-window flash attention, bf16x3, 2-stage cp.async,
// online softmax (exp2 domain) in registers, interior-tile mask fast path.
// CTA = 128 queries x 1 head, 8 warps (16 q-rows each).
// ===========================================================================
#define A_QH 0
#define A_QL 16384
#define A_ST(s) (32768 + (s) * 32768)
#define A_KH 0
#define A_KL 8192
#define A_VH 16384
#define A_VL 24576
#define ATT_SMEM (32768 + 2 * 32768)
#define SC2 (0.125f * 1.44269504f)   // score scale folded with log2(e)

__global__ __launch_bounds__(256, 2)
void attn_mma(const __nv_bfloat16* __restrict__ Qh,
              const __nv_bfloat16* __restrict__ Ql,
              const __nv_bfloat16* __restrict__ Kh,
              const __nv_bfloat16* __restrict__ Kl,
              const __nv_bfloat16* __restrict__ Vh,
              const __nv_bfloat16* __restrict__ Vl,
              __nv_bfloat16* __restrict__ Oh,
              __nv_bfloat16* __restrict__ Ol) {
    extern __shared__ char sm[];
    const uint32_t sbase = smem_u32(sm);

    const int tid = threadIdx.x;
    const int wid = tid >> 5, lane = tid & 31;
    const int qs = blockIdx.x * 128;
    const int hoff = blockIdx.y * HDIM;
    const int localr = lane & 7, sel = lane >> 3;

    // ---- stage Q tile (128 x 64 bf16 hi/lo), swizzled 128B rows ----
    {
        const int r = tid >> 1;
        const int half = (tid & 1) * 32;
        const size_t g = (size_t)(qs + r) * DD + hoff + half;
#pragma unroll
        for (int j = 0; j < 4; j++) {
            uint32_t off = SWZ((uint32_t)(r * 128 + (half + 8 * j) * 2));
            *(uint4*)(sm + A_QH + off) = *(const uint4*)&Qh[g + 8 * j];
            *(uint4*)(sm + A_QL + off) = *(const uint4*)&Ql[g + 8 * j];
        }
    }

    const int t0v = max(0, (512 - qs + 63) / 64);
    const int t1v = min(18, (SS + 512 - qs) / 64);

    const int svr = tid >> 2;
    const int svc = (tid & 3) * 16;

#define A_STAGE(t, s)                                                       \
    do {                                                                    \
        const int kabs_ = qs - 512 + 64 * (t) + svr;                        \
        const size_t g_ = (size_t)kabs_ * DD + hoff + svc;                  \
        const uint32_t stb_ = sbase + A_ST(s);                              \
        _Pragma("unroll")                                                   \
        for (int j = 0; j < 2; j++) {                                       \
            uint32_t off = SWZ((uint32_t)(svr * 128 + (svc + 8 * j) * 2));  \
            CPA16(stb_ + A_KH + off, &Kh[g_ + 8 * j], 16u);                 \
            CPA16(stb_ + A_KL + off, &Kl[g_ + 8 * j], 16u);                 \
            CPA16(stb_ + A_VH + off, &Vh[g_ + 8 * j], 16u);                 \
            CPA16(stb_ + A_VL + off, &Vl[g_ + 8 * j], 16u);                 \
        }                                                                   \
        CPA_COMMIT();                                                       \
    } while (0)

    const int q0 = qs + 16 * wid + (lane >> 2);
    const int q1 = q0 + 8;

    float m0 = -1e30f, m1 = -1e30f, l0 = 0.f, l1 = 0.f;
    float oacc[8][4];
#pragma unroll
    for (int nt = 0; nt < 8; nt++)
#pragma unroll
        for (int e = 0; e < 4; e++) oacc[nt][e] = 0.f;

    A_STAGE(t0v, 0);

    for (int t = t0v; t < t1v; t++) {
        const int s = (t - t0v) & 1;
        const int kt = qs - 512 + 64 * t;
        CPA_WAIT0();
        __syncthreads();
        if (t + 1 < t1v) A_STAGE(t + 1, s ^ 1);

        const uint32_t stb = sbase + A_ST(s);

        // ---- QK^T: S (16q x 64k per warp) ----
        float sacc[8][4];
#pragma unroll
        for (int nt = 0; nt < 8; nt++)
#pragma unroll
            for (int e = 0; e < 4; e++) sacc[nt][e] = 0.f;

#pragma unroll
        for (int kk = 0; kk < 64; kk += 16) {
            uint32_t qhf[4], qlf[4];
            {
                const int row = 16 * wid + localr + (sel & 1) * 8;
                const int kb = kk + (sel >> 1) * 8;
                const uint32_t off = SWZ((uint32_t)(row * 128 + kb * 2));
                LDSM_X4(qhf[0], qhf[1], qhf[2], qhf[3], sbase + A_QH + off);
                LDSM_X4(qlf[0], qlf[1], qlf[2], qlf[3], sbase + A_QL + off);
            }
            uint32_t khf[8][2], klf[8][2];
#pragma unroll
            for (int np = 0; np < 4; np++) {
                const int row = np * 16 + (sel >> 1) * 8 + localr;
                const int kb = kk + (sel & 1) * 8;
                const uint32_t off = SWZ((uint32_t)(row * 128 + kb * 2));
                uint32_t t0r, t1r, t2r, t3r;
                LDSM_X4(t0r, t1r, t2r, t3r, stb + A_KH + off);
                khf[2 * np][0] = t0r; khf[2 * np][1] = t1r;
                khf[2 * np + 1][0] = t2r; khf[2 * np + 1][1] = t3r;
                LDSM_X4(t0r, t1r, t2r, t3r, stb + A_KL + off);
                klf[2 * np][0] = t0r; klf[2 * np][1] = t1r;
                klf[2 * np + 1][0] = t2r; klf[2 * np + 1][1] = t3r;
            }
#pragma unroll
            for (int nt = 0; nt < 8; nt++) {
                MMA16816(sacc[nt], qhf, khf[nt]);
                MMA16816(sacc[nt], qhf, klf[nt]);
                MMA16816(sacc[nt], qlf, khf[nt]);
            }
        }

        // ---- scale to exp2 domain (+ window mask on edge tiles) + max ----
        float mx0 = -1e30f, mx1 = -1e30f;
        if (t < 2 || t > 15) {
            const int cb = kt + 2 * (lane & 3);
#pragma unroll
            for (int nt = 0; nt < 8; nt++) {
#pragma unroll
                for (int e = 0; e < 2; e++) {
                    const int kabs = cb + 8 * nt + e;
                    float s0 = ((kabs >= q0 - 512) & (kabs < q0 + 512))
                                   ? sacc[nt][e] * SC2 : -1e30f;
                    float s1 = ((kabs >= q1 - 512) & (kabs < q1 + 512))
                                   ? sacc[nt][e + 2] * SC2 : -1e30f;
                    sacc[nt][e] = s0; sacc[nt][e + 2] = s1;
                    mx0 = fmaxf(mx0, s0); mx1 = fmaxf(mx1, s1);
                }
            }
        } else {
#pragma unroll
            for (int nt = 0; nt < 8; nt++) {
#pragma unroll
                for (int e = 0; e < 2; e++) {
                    float s0 = sacc[nt][e] * SC2;
                    float s1 = sacc[nt][e + 2] * SC2;
                    sacc[nt][e] = s0; sacc[nt][e + 2] = s1;
                    mx0 = fmaxf(mx0, s0); mx1 = fmaxf(mx1, s1);
                }
            }
        }
        mx0 = fmaxf(mx0, __shfl_xor_sync(0xffffffffu, mx0, 1));
        mx0 = fmaxf(mx0, __shfl_xor_sync(0xffffffffu, mx0, 2));
        mx1 = fmaxf(mx1, __shfl_xor_sync(0xffffffffu, mx1, 1));
        mx1 = fmaxf(mx1, __shfl_xor_sync(0xffffffffu, mx1, 2));
        const float mn0 = fmaxf(m0, mx0), mn1 = fmaxf(m1, mx1);
        const float a0 = exp2f(m0 - mn0), a1 = exp2f(m1 - mn1);
        m0 = mn0; m1 = mn1;
        float rs0 = 0.f, rs1 = 0.f;
#pragma unroll
        for (int nt = 0; nt < 8; nt++) {
#pragma unroll
            for (int e = 0; e < 2; e++) {
                float p0 = (sacc[nt][e] > -5e29f) ? exp2f(sacc[nt][e] - mn0) : 0.f;
                float p1 = (sacc[nt][e + 2] > -5e29f) ? exp2f(sacc[nt][e + 2] - mn1) : 0.f;
                rs0 += p0; rs1 += p1;
                sacc[nt][e] = p0; sacc[nt][e + 2] = p1;
            }
        }
        l0 = l0 * a0 + rs0;
        l1 = l1 * a1 + rs1;
#pragma unroll
        for (int nt = 0; nt < 8; nt++) {
            oacc[nt][0] *= a0; oacc[nt][1] *= a0;
            oacc[nt][2] *= a1; oacc[nt][3] *= a1;
        }

        // ---- PV: O += P * V ----
#pragma unroll
        for (int kc = 0; kc < 4; kc++) {
            uint32_t pah[4], pal[4];
            split2(sacc[2 * kc][0], sacc[2 * kc][1], pah[0], pal[0]);
            split2(sacc[2 * kc][2], sacc[2 * kc][3], pah[1], pal[1]);
            split2(sacc[2 * kc + 1][0], sacc[2 * kc + 1][1], pah[2], pal[2]);
            split2(sacc[2 * kc + 1][2], sacc[2 * kc + 1][3], pah[3], pal[3]);

            uint32_t vhf[8][2], vlf[8][2];
#pragma unroll
            for (int ntp = 0; ntp < 4; ntp++) {
                const int key = 16 * kc + (sel & 1) * 8 + localr;
                const int dim = (2 * ntp + (sel >> 1)) * 8;
                const uint32_t off = SWZ((uint32_t)(key * 128 + dim * 2));
                uint32_t t0r, t1r, t2r, t3r;
                LDSM_X4_T(t0r, t1r, t2r, t3r, stb + A_VH + off);
                vhf[2 * ntp][0] = t0r; vhf[2 * ntp][1] = t1r;
                vhf[2 * ntp + 1][0] = t2r; vhf[2 * ntp + 1][1] = t3r;
                LDSM_X4_T(t0r, t1r, t2r, t3r, stb + A_VL + off);
                vlf[2 * ntp][0] = t0r; vlf[2 * ntp][1] = t1r;
                vlf[2 * ntp + 1][0] = t2r; vlf[2 * ntp + 1][1] = t3r;
            }
#pragma unroll
            for (int nt = 0; nt < 8; nt++) {
                MMA16816(oacc[nt], pah, vhf[nt]);
                MMA16816(oacc[nt], pah, vlf[nt]);
                MMA16816(oacc[nt], pal, vhf[nt]);
            }
        }
    }

    // ---- epilogue: normalize, blend weight, write bf16 hi/lo ----
    l0 += __shfl_xor_sync(0xffffffffu, l0, 1);
    l0 += __shfl_xor_sync(0xffffffffu, l0, 2);
    l1 += __shfl_xor_sync(0xffffffffu, l1, 1);
    l1 += __shfl_xor_sync(0xffffffffu, l1, 2);
    float w0 = 1.f, w1 = 1.f;
    if (q0 >= SS - 128) w0 = 1.f + (float)(q0 - (SS - 128)) * (1.f / 127.f);
    if (q1 >= SS - 128) w1 = 1.f + (float)(q1 - (SS - 128)) * (1.f / 127.f);
    const float sc0 = w0 / l0, sc1 = w1 / l1;
    const int ec = 2 * (lane & 3);
#pragma unroll
    for (int nt = 0; nt < 8; nt++) {
        const size_t i0 = (size_t)q0 * DD + hoff + 8 * nt + ec;
        const size_t i1 = (size_t)q1 * DD + hoff + 8 * nt + ec;
        uint32_t h0, l0u, h1, l1u;
        split2(oacc[nt][0] * sc0, oacc[nt][1] * sc0, h0, l0u);
        split2(oacc[nt][2] * sc1, oacc[nt][3] * sc1, h1, l1u);
        *(uint32_t*)&Oh[i0] = h0;
        *(uint32_t*)&Ol[i0] = l0u;
        *(uint32_t*)&Oh[i1] = h1;
        *(uint32_t*)&Ol[i1] = l1u;
    }
}

// ===========================================================================
extern "C" void kernel_launch(void* const* d_in, const int* in_sizes, int n_in,
                              void* d_out, int out_size) {
    const float* x = nullptr;
    const float* Wm[4] = {nullptr, nullptr, nullptr, nullptr};
    const float* bm[4] = {nullptr, nullptr, nullptr, nullptr};
    int nw = 0, nb = 0;
    for (int i = 0; i < n_in; i++) {
        const float* p = (const float*)d_in[i];
        if (in_sizes[i] == SS * DD) x = p;
        else if (in_sizes[i] == DD * DD) { if (nw < 4) Wm[nw++] = p; }
        else if (in_sizes[i] == DD) { if (nb < 4) bm[nb++] = p; }
    }
    float* out = (float*)d_out;

    __nv_bfloat16 *xh, *xl, *Wh, *Wl, *Qh, *Ql, *Kh, *Kl, *Vh, *Vl, *Oh, *Ol;
    cudaGetSymbolAddress((void**)&xh, g_xh);
    cudaGetSymbolAddress((void**)&xl, g_xl);
    cudaGetSymbolAddress((void**)&Wh, g_Wh);
    cudaGetSymbolAddress((void**)&Wl, g_Wl);
    cudaGetSymbolAddress((void**)&Qh, g_Qh);
    cudaGetSymbolAddress((void**)&Ql, g_Ql);
    cudaGetSymbolAddress((void**)&Kh, g_Kh);
    cudaGetSymbolAddress((void**)&Kl, g_Kl);
    cudaGetSymbolAddress((void**)&Vh, g_Vh);
    cudaGetSymbolAddress((void**)&Vl, g_Vl);
    cudaGetSymbolAddress((void**)&Oh, g_Oh);
    cudaGetSymbolAddress((void**)&Ol, g_Ol);

    // ---- fused split of x and all 4 weights (one launch) ----
    const int NTOT = NX8 + 4 * NW8;
    split_all<<<(NTOT + 255) / 256, 256>>>(x, Wm[0], Wm[1], Wm[2], Wm[3],
                                           xh, xl, Wh, Wl);

    cudaFuncSetAttribute(gemm_qkv, cudaFuncAttributeMaxDynamicSharedMemorySize,
                         GEMM_SMEM);
    cudaFuncSetAttribute(gemm_out, cudaFuncAttributeMaxDynamicSharedMemorySize,
                         GEMM_SMEM);
    cudaFuncSetAttribute(attn_mma, cudaFuncAttributeMaxDynamicSharedMemorySize,
                         ATT_SMEM);

    // ---- fused Q/K/V projections ----
    QKVArgs qa;
    qa.Bh[0] = Wh;                     qa.Bl[0] = Wl;
    qa.Bh[1] = Wh + (size_t)1 * DD * DD; qa.Bl[1] = Wl + (size_t)1 * DD * DD;
    qa.Bh[2] = Wh + (size_t)2 * DD * DD; qa.Bl[2] = Wl + (size_t)2 * DD * DD;
    qa.bias[0] = bm[0]; qa.bias[1] = bm[1]; qa.bias[2] = bm[2];
    qa.Ch[0] = Qh; qa.Cl[0] = Ql;
    qa.Ch[1] = Kh; qa.Cl[1] = Kl;
    qa.Ch[2] = Vh; qa.Cl[2] = Vl;

    dim3 qkvgrid(DD / 128, SS / 128, 3);
    gemm_qkv<<<qkvgrid, 256, GEMM_SMEM>>>(xh, xl, qa);

    attn_mma<<<dim3(SS / 128, HH), 256, ATT_SMEM>>>(Qh, Ql, Kh, Kl, Vh, Vl,
                                                    Oh, Ol);

    dim3 ogrid(DD / 128, SS / 128);
    gemm_out<<<ogrid, 256, GEMM_SMEM>>>(Oh, Ol, Wh + (size_t)3 * DD * DD,
                                        Wl + (size_t)3 * DD * DD, bm[3], out);
}